// round 11
// baseline (speedup 1.0000x reference)
#include <cuda_runtime.h>
#include <cuda_bf16.h>
#include <math.h>
#include <stdint.h>

#define NB     128     // batches
#define NG     8000    // plane waves (20^3)
#define NPTS   8000    // points
#define NGR    20      // grid per dim
#define KC     32      // K per stage
#define NSTAGE 250     // NG / KC
#define NTILE  64      // points per CTA
#define NCTA   125     // NPTS / NTILE
#define NT     320     // 8 consumer warps (4m x 2n) + 2 producer warps

// A stage chunk: 6 variants x 128 rows x 80B = 61440 B
#define STG_BYTES 61440
#define AS_VAR    10240
#define B_OFF     122880                     // after 2 A buffers
#define BS_BUF    30720                      // 6 variants x 64 rows x 80B
#define BS_VAR    5120
#define SE_OFF    184320                     // 3 x 64 x 20 x float2 = 30720
#define MB_OFF    215040                     // 2 mbarriers
#define SM_TOTAL  215072

__device__ float d_B[9];
__device__ float d_scale;
// stage-major, ldmatrix-ready (80B rows, pad zeroed):
// d_A2[((s*6 + v)*128 + row)*40 + g]   v: 0 crh 1 crl 2 cih 3 cil 4 csh 5 csl
__device__ __align__(128) __nv_bfloat16 d_A2[(size_t)NSTAGE * 6 * NB * 40];  // 15.36 MB

// ---------------- helpers ----------------
__device__ __forceinline__ uint32_t smem_u32(const void* p) {
    uint32_t a;
    asm("{ .reg .u64 t; cvta.to.shared.u64 t, %1; cvt.u32.u64 %0, t; }" : "=r"(a) : "l"(p));
    return a;
}
__device__ __forceinline__ float2 cmul(float2 a, float2 b) {
    return make_float2(a.x*b.x - a.y*b.y, a.x*b.y + a.y*b.x);
}

#define MMA16816(d, a, b0, b1) \
    asm volatile("mma.sync.aligned.m16n8k16.row.col.f32.bf16.bf16.f32 " \
        "{%0,%1,%2,%3}, {%4,%5,%6,%7}, {%8,%9}, {%0,%1,%2,%3};" \
        : "+f"((d)[0]), "+f"((d)[1]), "+f"((d)[2]), "+f"((d)[3]) \
        : "r"((a)[0]), "r"((a)[1]), "r"((a)[2]), "r"((a)[3]), "r"(b0), "r"(b1))

#define LDSM_X4(r, addr) \
    asm volatile("ldmatrix.sync.aligned.m8n8.x4.shared.b16 {%0,%1,%2,%3}, [%4];" \
        : "=r"((r)[0]), "=r"((r)[1]), "=r"((r)[2]), "=r"((r)[3]) : "r"(addr))

#define BAR_SYNC(id)   asm volatile("bar.sync %0, %1;"   :: "r"(id), "r"(NT) : "memory")
#define BAR_ARRIVE(id) asm volatile("bar.arrive %0, %1;" :: "r"(id), "r"(NT) : "memory")

#define MBAR_WAIT(mbar, parity) do { \
    uint32_t _m = (mbar); uint32_t _p = (parity); uint32_t _d; \
    asm volatile("{ .reg .pred p; mbarrier.try_wait.parity.acquire.cta.shared::cta.b64 p, [%1], %2; selp.b32 %0, 1, 0, p; }" \
        : "=r"(_d) : "r"(_m), "r"(_p) : "memory"); \
    if (!_d) { \
        asm volatile("{ .reg .pred P1; WL_%=: mbarrier.try_wait.parity.acquire.cta.shared::cta.b64 P1, [%0], %1, 0x989680; @P1 bra.uni WD_%=; bra.uni WL_%=; WD_%=: }" \
            :: "r"(_m), "r"(_p) : "memory"); \
    } \
} while (0)

// ---------------- prep: setup (block 0) + stage-major bf16 splits ----------------
__global__ void prep_kernel(const float* __restrict__ cre, const float* __restrict__ cim,
                            const float* __restrict__ A) {
    if (blockIdx.x == 0 && threadIdx.x == 0) {
        double a00=A[0],a01=A[1],a02=A[2];
        double a10=A[3],a11=A[4],a12=A[5];
        double a20=A[6],a21=A[7],a22=A[8];
        double c00 =  (a11*a22 - a12*a21);
        double c01 = -(a10*a22 - a12*a20);
        double c02 =  (a10*a21 - a11*a20);
        double c10 = -(a01*a22 - a02*a21);
        double c11 =  (a00*a22 - a02*a20);
        double c12 = -(a00*a21 - a01*a20);
        double c20 =  (a01*a12 - a02*a11);
        double c21 = -(a00*a12 - a02*a10);
        double c22 =  (a00*a11 - a01*a10);
        double det = a00*c00 + a01*c01 + a02*c02;
        double tp  = 6.283185307179586476925286766559;
        double s   = tp / det;
        d_B[0]=(float)(c00*s); d_B[1]=(float)(c01*s); d_B[2]=(float)(c02*s);
        d_B[3]=(float)(c10*s); d_B[4]=(float)(c11*s); d_B[5]=(float)(c12*s);
        d_B[6]=(float)(c20*s); d_B[7]=(float)(c21*s); d_B[8]=(float)(c22*s);
        d_scale = (float)(1.0 / sqrt(fabs(det)));
    }
    int b = blockIdx.x;
    for (int g = threadIdx.x; g < NG; g += 256) {
        int s  = g >> 5;
        int gl = g & 31;
        float vr = cre[(size_t)b * NG + g];
        float vi = cim[(size_t)b * NG + g];
        float vs = vr + vi;
        __nv_bfloat16 rh = __float2bfloat16(vr);
        __nv_bfloat16 rl = __float2bfloat16(vr - __bfloat162float(rh));
        __nv_bfloat16 ih = __float2bfloat16(vi);
        __nv_bfloat16 il = __float2bfloat16(vi - __bfloat162float(ih));
        __nv_bfloat16 sh = __float2bfloat16(vs);
        __nv_bfloat16 sl = __float2bfloat16(vs - __bfloat162float(sh));
        size_t base = ((size_t)s * 6 * NB + b) * 40 + gl;
        d_A2[base + (size_t)0 * NB * 40] = rh;
        d_A2[base + (size_t)1 * NB * 40] = rl;
        d_A2[base + (size_t)2 * NB * 40] = ih;
        d_A2[base + (size_t)3 * NB * 40] = il;
        d_A2[base + (size_t)4 * NB * 40] = sh;
        d_A2[base + (size_t)5 * NB * 40] = sl;
    }
    // zero the 16B row padding (deterministic every call)
    __nv_bfloat16 z = __float2bfloat16(0.0f);
    for (int t = threadIdx.x; t < NSTAGE * 6 * 8; t += 256) {
        int s = t / 48;
        int rem = t - s * 48;
        int v = rem >> 3;
        int q = rem & 7;
        d_A2[(((size_t)s * 6 + v) * NB + b) * 40 + 32 + q] = z;
    }
}

// ---------------- mma building block: m32 x n32 x k16 with hi/lo split ----------------
__device__ __forceinline__ void mma_set(
    float S[2][4][4], uint32_t aH, uint32_t aL, uint32_t bH, uint32_t bL)
{
    uint32_t ah[2][4], al[2][4], bh[2][4], bl[2][4];
    #pragma unroll
    for (int mt = 0; mt < 2; mt++) {
        LDSM_X4(ah[mt], aH + mt * 16 * 80);
        LDSM_X4(al[mt], aL + mt * 16 * 80);
    }
    #pragma unroll
    for (int np = 0; np < 2; np++) {
        LDSM_X4(bh[np], bH + np * 16 * 80);
        LDSM_X4(bl[np], bL + np * 16 * 80);
    }
    #pragma unroll
    for (int mt = 0; mt < 2; mt++) {
        #pragma unroll
        for (int nt = 0; nt < 4; nt++) {
            int np = nt >> 1, q = (nt & 1) * 2;
            MMA16816(S[mt][nt], ah[mt], bh[np][q], bh[np][q+1]);   // hi*hi
            MMA16816(S[mt][nt], al[mt], bh[np][q], bh[np][q+1]);   // lo*hi
            MMA16816(S[mt][nt], ah[mt], bl[np][q], bl[np][q+1]);   // hi*lo
        }
    }
}

// ---------------- main kernel: warp-specialized producer/consumer ----------------
__global__ void __launch_bounds__(NT, 1)
mma_kernel(const float* __restrict__ r, const float* __restrict__ kg,
           float* __restrict__ out, int out_elems)
{
    extern __shared__ char smem[];
    uint32_t sb = smem_u32(smem);
    const int tid  = threadIdx.x;
    const int wid  = tid >> 5;
    const int lane = tid & 31;
    const int p0   = blockIdx.x * NTILE;
    const uint32_t mbar0 = sb + MB_OFF;
    const uint32_t mbar1 = sb + MB_OFF + 8;

    // e tables: se[(d*64+p)*20+i] = exp(i * m(i) * (B_d . r_p))  (all 320 threads)
    float2* se = (float2*)(smem + SE_OFF);
    for (int t = tid; t < 3 * NTILE * NGR; t += NT) {
        int d   = t / (NTILE * NGR);
        int rem = t - d * NTILE * NGR;
        int p   = rem / NGR;
        int i   = rem - p * NGR;
        int m   = (i < NGR/2) ? i : i - NGR;
        const float* rp = r + (p0 + p) * 3;
        float u = d_B[3*d]*rp[0] + d_B[3*d+1]*rp[1] + d_B[3*d+2]*rp[2];
        float sv, cv;
        sincosf((float)m * u, &sv, &cv);
        se[(d * NTILE + p) * NGR + i] = make_float2(cv, sv);
    }
    if (tid == 0) {
        asm volatile("mbarrier.init.shared.b64 [%0], %1;" :: "r"(mbar0), "r"(1u) : "memory");
        asm volatile("mbarrier.init.shared.b64 [%0], %1;" :: "r"(mbar1), "r"(1u) : "memory");
    }
    __syncthreads();

    if (wid < 8) {
        // ================= CONSUMERS (warps 0-7) =================
        float S1[2][4][4], S2[2][4][4], S3[2][4][4];
        #pragma unroll
        for (int mt = 0; mt < 2; mt++)
            #pragma unroll
            for (int nt = 0; nt < 4; nt++)
                #pragma unroll
                for (int q = 0; q < 4; q++) { S1[mt][nt][q]=0.f; S2[mt][nt][q]=0.f; S3[mt][nt][q]=0.f; }

        const uint32_t aRowOff = (lane & 15) * 80 + (lane >> 4) * 16;
        const uint32_t bRowOff = (((lane >> 4) & 1) * 8 + (lane & 7)) * 80 + ((lane >> 3) & 1) * 16;
        const int m0 = (wid & 3) * 32;
        const int n0 = (wid >> 2) * 32;
        const uint32_t amBase = (uint32_t)m0 * 80 + aRowOff;
        const uint32_t bnBase = (uint32_t)n0 * 80 + bRowOff;

        for (int s = 0; s < NSTAGE; s++) {
            const int cur = s & 1;
            const uint32_t aBuf = sb + cur * STG_BYTES;
            const uint32_t bBuf = sb + B_OFF + cur * BS_BUF;

            BAR_SYNC(1);                                        // B(s) ready
            MBAR_WAIT(cur ? mbar1 : mbar0, (uint32_t)((s >> 1) & 1));  // A(s) landed

            #pragma unroll
            for (int k16 = 0; k16 < 2; k16++) {
                uint32_t kb = k16 * 32;
                mma_set(S1, aBuf + 0*AS_VAR + amBase + kb, aBuf + 1*AS_VAR + amBase + kb,
                            bBuf + 0*BS_VAR + bnBase + kb, bBuf + 1*BS_VAR + bnBase + kb);
                mma_set(S2, aBuf + 2*AS_VAR + amBase + kb, aBuf + 3*AS_VAR + amBase + kb,
                            bBuf + 2*BS_VAR + bnBase + kb, bBuf + 3*BS_VAR + bnBase + kb);
                mma_set(S3, aBuf + 4*AS_VAR + amBase + kb, aBuf + 5*AS_VAR + amBase + kb,
                            bBuf + 4*BS_VAR + bnBase + kb, bBuf + 5*BS_VAR + bnBase + kb);
            }
            BAR_ARRIVE(2);                                      // MMA(s) done
        }

        // ---- epilogue ----
        const bool cplx = (out_elems >= 2 * NB * NPTS);
        const float scale = d_scale;
        #pragma unroll
        for (int mt = 0; mt < 2; mt++) {
            #pragma unroll
            for (int nt = 0; nt < 4; nt++) {
                #pragma unroll
                for (int q = 0; q < 4; q++) {
                    float v1 = S1[mt][nt][q], v2 = S2[mt][nt][q], v3 = S3[mt][nt][q];
                    float Re = v1 - v2;
                    float Im = v3 - v1 - v2;
                    int b = m0 + mt * 16 + (lane >> 2) + (q >> 1) * 8;
                    int p = p0 + n0 + nt * 8 + (lane & 3) * 2 + (q & 1);
                    int kq = (b >> 4) & 3;
                    const float* rp = r + p * 3;
                    float ang = kg[3*kq]*rp[0] + kg[3*kq+1]*rp[1] + kg[3*kq+2]*rp[2];
                    float sv, cv;
                    sincosf(ang, &sv, &cv);
                    float ore = (Re * cv - Im * sv) * scale;
                    float oim = (Re * sv + Im * cv) * scale;
                    size_t idx = (size_t)b * NPTS + p;
                    if (cplx) ((float2*)out)[idx] = make_float2(ore, oim);
                    else      out[idx] = ore;
                }
            }
        }
    } else {
        // ================= PRODUCERS (warps 8-9) =================
        const int w = wid - 8;              // 0 or 1 -> points w*32 .. w*32+31
        const int gl = lane;                // g within stage

        // prologue: issue bulk copies for stages 0 and 1
        if (tid == 256) {
            asm volatile("mbarrier.arrive.expect_tx.shared.b64 _, [%0], %1;"
                         :: "r"(mbar0), "r"((uint32_t)STG_BYTES) : "memory");
            asm volatile("cp.async.bulk.shared::cluster.global.mbarrier::complete_tx::bytes [%0], [%1], %2, [%3];"
                         :: "r"(sb), "l"((const char*)d_A2), "r"((uint32_t)STG_BYTES), "r"(mbar0) : "memory");
            asm volatile("mbarrier.arrive.expect_tx.shared.b64 _, [%0], %1;"
                         :: "r"(mbar1), "r"((uint32_t)STG_BYTES) : "memory");
            asm volatile("cp.async.bulk.shared::cluster.global.mbarrier::complete_tx::bytes [%0], [%1], %2, [%3];"
                         :: "r"(sb + STG_BYTES), "l"((const char*)d_A2 + STG_BYTES), "r"((uint32_t)STG_BYTES), "r"(mbar1) : "memory");
        }

        for (int s = 0; s < NSTAGE; s++) {
            if (s >= 2) {
                BAR_SYNC(2);   // consumers finished MMA(s-2): A/B bufs (s&1) free
                if (tid == 256) {
                    uint32_t nb = s & 1;
                    uint32_t mb = nb ? mbar1 : mbar0;
                    asm volatile("mbarrier.arrive.expect_tx.shared.b64 _, [%0], %1;"
                                 :: "r"(mb), "r"((uint32_t)STG_BYTES) : "memory");
                    const char* src = (const char*)d_A2 + (size_t)s * STG_BYTES;
                    asm volatile("cp.async.bulk.shared::cluster.global.mbarrier::complete_tx::bytes [%0], [%1], %2, [%3];"
                                 :: "r"(sb + nb * STG_BYTES), "l"(src), "r"((uint32_t)STG_BYTES), "r"(mb) : "memory");
                }
            }
            // generate B(s) phases: 32 points x this lane's g
            {
                int g  = s * KC + gl;
                int i1 = g / 400;
                int i2 = (g / 20) % 20;
                int i3 = g % 20;
                char* bptr = smem + B_OFF + (s & 1) * BS_BUF;
                #pragma unroll 4
                for (int pi = 0; pi < 32; pi++) {
                    int p = w * 32 + pi;
                    float2 e1 = se[(0 * NTILE + p) * NGR + i1];
                    float2 e2 = se[(1 * NTILE + p) * NGR + i2];
                    float2 e3 = se[(2 * NTILE + p) * NGR + i3];
                    float2 ph = cmul(cmul(e1, e2), e3);
                    float pr = ph.x, pim = ph.y, ps = pr + pim;
                    __nv_bfloat16 prh = __float2bfloat16(pr);
                    __nv_bfloat16 prl = __float2bfloat16(pr - __bfloat162float(prh));
                    __nv_bfloat16 pih = __float2bfloat16(pim);
                    __nv_bfloat16 pil = __float2bfloat16(pim - __bfloat162float(pih));
                    __nv_bfloat16 psh = __float2bfloat16(ps);
                    __nv_bfloat16 psl = __float2bfloat16(ps - __bfloat162float(psh));
                    uint32_t off = (uint32_t)p * 80 + gl * 2;
                    *(__nv_bfloat16*)(bptr + 0 * BS_VAR + off) = prh;
                    *(__nv_bfloat16*)(bptr + 1 * BS_VAR + off) = prl;
                    *(__nv_bfloat16*)(bptr + 2 * BS_VAR + off) = pih;
                    *(__nv_bfloat16*)(bptr + 3 * BS_VAR + off) = pil;
                    *(__nv_bfloat16*)(bptr + 4 * BS_VAR + off) = psh;
                    *(__nv_bfloat16*)(bptr + 5 * BS_VAR + off) = psl;
                }
            }
            BAR_ARRIVE(1);     // B(s) ready
        }
    }
}

extern "C" void kernel_launch(void* const* d_in, const int* in_sizes, int n_in,
                              void* d_out, int out_size) {
    const float* A   = nullptr;
    const float* kg  = nullptr;
    const float* r   = nullptr;
    const float* cre = nullptr;
    const float* cim = nullptr;
    for (int i = 0; i < n_in; i++) {
        const float* p = (const float*)d_in[i];
        long long sz = in_sizes[i];
        if (sz == 9 || sz == 36)               A = p;
        else if (sz == 12 || sz == 48)         kg = p;
        else if (sz == 24000 || sz == 96000)   r = p;
        else if (sz == (long long)NB * NG || sz == (long long)NB * NG * 4) {
            if (!cre) cre = p; else cim = p;
        }
    }
    if (!A || !kg || !r || !cre || !cim) {
        if (n_in >= 5) {
            A   = (const float*)d_in[0];
            kg  = (const float*)d_in[1];
            cre = (const float*)d_in[2];
            cim = (const float*)d_in[3];
            r   = (const float*)d_in[4];
        } else {
            return;
        }
    }

    static bool attr_set = false;
    if (!attr_set) {
        cudaFuncSetAttribute(mma_kernel, cudaFuncAttributeMaxDynamicSharedMemorySize, SM_TOTAL);
        attr_set = true;
    }

    prep_kernel<<<NB, 256>>>(cre, cim, A);
    mma_kernel<<<NCTA, NT, SM_TOTAL>>>(r, kg, (float*)d_out, out_size);
}

// round 13
// speedup vs baseline: 1.2061x; 1.2061x over previous
#include <cuda_runtime.h>
#include <cuda_bf16.h>
#include <math.h>
#include <stdint.h>

#define NB     128     // batches
#define NG     8000    // plane waves (20^3)
#define NPTS   8000    // points
#define NGR    20      // grid per dim
#define KC     32      // K per stage
#define NSTAGE 250     // NG / KC
#define NTILE  64      // points per CTA
#define NCTA   125     // NPTS / NTILE
#define NT     256     // threads (8 warps, 4m x 2n grid: m32 x n32 per warp)

// A stage chunk: 6 variants x 128 rows x 80B (64B data + 16B pad) = 61440 B
#define STG_BYTES 61440
#define AS_VAR    10240
#define B_OFF     122880                     // after 2 A buffers
#define BS_BUF    30720                      // 6 variants x 64 rows x 80B
#define BS_VAR    5120
#define SE_OFF    184320                     // 3 x 64 x 20 x float2 = 30720
#define MB_OFF    215040                     // 2 mbarriers
#define SM_TOTAL  215072

__device__ float d_B[9];
__device__ float d_scale;
// stage-major, ldmatrix-ready (80B rows, pad zeroed):
// d_A2[((s*6 + v)*128 + row)*40 + g]   v: 0 crh 1 crl 2 cih 3 cil 4 csh 5 csl
__device__ __align__(128) __nv_bfloat16 d_A2[(size_t)NSTAGE * 6 * NB * 40];  // 15.36 MB

// ---------------- helpers ----------------
__device__ __forceinline__ uint32_t smem_u32(const void* p) {
    uint32_t a;
    asm("{ .reg .u64 t; cvta.to.shared.u64 t, %1; cvt.u32.u64 %0, t; }" : "=r"(a) : "l"(p));
    return a;
}
__device__ __forceinline__ float2 cmul(float2 a, float2 b) {
    return make_float2(a.x*b.x - a.y*b.y, a.x*b.y + a.y*b.x);
}

#define MMA16816(d, a, b0, b1) \
    asm volatile("mma.sync.aligned.m16n8k16.row.col.f32.bf16.bf16.f32 " \
        "{%0,%1,%2,%3}, {%4,%5,%6,%7}, {%8,%9}, {%0,%1,%2,%3};" \
        : "+f"((d)[0]), "+f"((d)[1]), "+f"((d)[2]), "+f"((d)[3]) \
        : "r"((a)[0]), "r"((a)[1]), "r"((a)[2]), "r"((a)[3]), "r"(b0), "r"(b1))

#define LDSM_X4(r, addr) \
    asm volatile("ldmatrix.sync.aligned.m8n8.x4.shared.b16 {%0,%1,%2,%3}, [%4];" \
        : "=r"((r)[0]), "=r"((r)[1]), "=r"((r)[2]), "=r"((r)[3]) : "r"(addr))

#define MBAR_WAIT(mbar, parity) do { \
    uint32_t _m = (mbar); uint32_t _p = (parity); uint32_t _d; \
    asm volatile("{ .reg .pred p; mbarrier.try_wait.parity.acquire.cta.shared::cta.b64 p, [%1], %2; selp.b32 %0, 1, 0, p; }" \
        : "=r"(_d) : "r"(_m), "r"(_p) : "memory"); \
    if (!_d) { \
        asm volatile("{ .reg .pred P1; WL_%=: mbarrier.try_wait.parity.acquire.cta.shared::cta.b64 P1, [%0], %1, 0x989680; @P1 bra.uni WD_%=; bra.uni WL_%=; WD_%=: }" \
            :: "r"(_m), "r"(_p) : "memory"); \
    } \
} while (0)

// ---------------- prep: setup (block 0) + stage-major bf16 splits ----------------
__global__ void prep_kernel(const float* __restrict__ cre, const float* __restrict__ cim,
                            const float* __restrict__ A) {
    if (blockIdx.x == 0 && threadIdx.x == 0) {
        double a00=A[0],a01=A[1],a02=A[2];
        double a10=A[3],a11=A[4],a12=A[5];
        double a20=A[6],a21=A[7],a22=A[8];
        double c00 =  (a11*a22 - a12*a21);
        double c01 = -(a10*a22 - a12*a20);
        double c02 =  (a10*a21 - a11*a20);
        double c10 = -(a01*a22 - a02*a21);
        double c11 =  (a00*a22 - a02*a20);
        double c12 = -(a00*a21 - a01*a20);
        double c20 =  (a01*a12 - a02*a11);
        double c21 = -(a00*a12 - a02*a10);
        double c22 =  (a00*a11 - a01*a10);
        double det = a00*c00 + a01*c01 + a02*c02;
        double tp  = 6.283185307179586476925286766559;
        double s   = tp / det;
        d_B[0]=(float)(c00*s); d_B[1]=(float)(c01*s); d_B[2]=(float)(c02*s);
        d_B[3]=(float)(c10*s); d_B[4]=(float)(c11*s); d_B[5]=(float)(c12*s);
        d_B[6]=(float)(c20*s); d_B[7]=(float)(c21*s); d_B[8]=(float)(c22*s);
        d_scale = (float)(1.0 / sqrt(fabs(det)));
    }
    int b = blockIdx.x;
    for (int g = threadIdx.x; g < NG; g += 256) {
        int s  = g >> 5;
        int gl = g & 31;
        float vr = cre[(size_t)b * NG + g];
        float vi = cim[(size_t)b * NG + g];
        float vs = vr + vi;
        __nv_bfloat16 rh = __float2bfloat16(vr);
        __nv_bfloat16 rl = __float2bfloat16(vr - __bfloat162float(rh));
        __nv_bfloat16 ih = __float2bfloat16(vi);
        __nv_bfloat16 il = __float2bfloat16(vi - __bfloat162float(ih));
        __nv_bfloat16 sh = __float2bfloat16(vs);
        __nv_bfloat16 sl = __float2bfloat16(vs - __bfloat162float(sh));
        size_t base = ((size_t)s * 6 * NB + b) * 40 + gl;
        d_A2[base + (size_t)0 * NB * 40] = rh;
        d_A2[base + (size_t)1 * NB * 40] = rl;
        d_A2[base + (size_t)2 * NB * 40] = ih;
        d_A2[base + (size_t)3 * NB * 40] = il;
        d_A2[base + (size_t)4 * NB * 40] = sh;
        d_A2[base + (size_t)5 * NB * 40] = sl;
    }
    // zero the 16B row padding (deterministic every call)
    __nv_bfloat16 z = __float2bfloat16(0.0f);
    for (int t = threadIdx.x; t < NSTAGE * 6 * 8; t += 256) {
        int s = t / 48;
        int rem = t - s * 48;
        int v = rem >> 3;
        int q = rem & 7;
        d_A2[(((size_t)s * 6 + v) * NB + b) * 40 + 32 + q] = z;
    }
}

// ---------------- B phase generation for one stage (all 8 warps, 8 pts each) ----------------
__device__ __forceinline__ void bgen(char* smem, const float2* se, int s,
                                     int wid, int lane)
{
    int gl = lane;
    int g  = s * KC + gl;
    int i1 = g / 400;
    int i2 = (g / 20) % 20;
    int i3 = g % 20;
    char* bptr = smem + B_OFF + (s & 1) * BS_BUF;
    #pragma unroll
    for (int pi = 0; pi < 8; pi++) {
        int p = wid * 8 + pi;
        float2 e1 = se[(0 * NTILE + p) * NGR + i1];
        float2 e2 = se[(1 * NTILE + p) * NGR + i2];
        float2 e3 = se[(2 * NTILE + p) * NGR + i3];
        float2 ph = cmul(cmul(e1, e2), e3);
        float pr = ph.x, pim = ph.y, ps = pr + pim;
        __nv_bfloat16 prh = __float2bfloat16(pr);
        __nv_bfloat16 prl = __float2bfloat16(pr - __bfloat162float(prh));
        __nv_bfloat16 pih = __float2bfloat16(pim);
        __nv_bfloat16 pil = __float2bfloat16(pim - __bfloat162float(pih));
        __nv_bfloat16 psh = __float2bfloat16(ps);
        __nv_bfloat16 psl = __float2bfloat16(ps - __bfloat162float(psh));
        uint32_t off = (uint32_t)p * 80 + gl * 2;
        *(__nv_bfloat16*)(bptr + 0 * BS_VAR + off) = prh;
        *(__nv_bfloat16*)(bptr + 1 * BS_VAR + off) = prl;
        *(__nv_bfloat16*)(bptr + 2 * BS_VAR + off) = pih;
        *(__nv_bfloat16*)(bptr + 3 * BS_VAR + off) = pil;
        *(__nv_bfloat16*)(bptr + 4 * BS_VAR + off) = psh;
        *(__nv_bfloat16*)(bptr + 5 * BS_VAR + off) = psl;
    }
}

// ---------------- mma building block: m32 x n32 x k16 with hi/lo split ----------------
__device__ __forceinline__ void mma_set(
    float S[2][4][4], uint32_t aH, uint32_t aL, uint32_t bH, uint32_t bL)
{
    uint32_t ah[2][4], al[2][4], bh[2][4], bl[2][4];
    #pragma unroll
    for (int mt = 0; mt < 2; mt++) {
        LDSM_X4(ah[mt], aH + mt * 16 * 80);
        LDSM_X4(al[mt], aL + mt * 16 * 80);
    }
    #pragma unroll
    for (int np = 0; np < 2; np++) {
        LDSM_X4(bh[np], bH + np * 16 * 80);
        LDSM_X4(bl[np], bL + np * 16 * 80);
    }
    #pragma unroll
    for (int mt = 0; mt < 2; mt++) {
        #pragma unroll
        for (int nt = 0; nt < 4; nt++) {
            int np = nt >> 1, q = (nt & 1) * 2;
            MMA16816(S[mt][nt], ah[mt], bh[np][q], bh[np][q+1]);   // hi*hi
            MMA16816(S[mt][nt], al[mt], bh[np][q], bh[np][q+1]);   // lo*hi
            MMA16816(S[mt][nt], ah[mt], bl[np][q], bl[np][q+1]);   // hi*lo
        }
    }
}

// ---------------- main kernel ----------------
__global__ void __launch_bounds__(NT, 1)
mma_kernel(const float* __restrict__ r, const float* __restrict__ kg,
           float* __restrict__ out, int out_elems)
{
    extern __shared__ char smem[];
    uint32_t sb = smem_u32(smem);
    const int tid  = threadIdx.x;
    const int wid  = tid >> 5;
    const int lane = tid & 31;
    const int p0   = blockIdx.x * NTILE;
    const uint32_t mbar0 = sb + MB_OFF;
    const uint32_t mbar1 = sb + MB_OFF + 8;

    // e tables: se[(d*64+p)*20+i] = exp(i * m(i) * (B_d . r_p))
    float2* se = (float2*)(smem + SE_OFF);
    for (int t = tid; t < 3 * NTILE * NGR; t += NT) {
        int d   = t / (NTILE * NGR);
        int rem = t - d * NTILE * NGR;
        int p   = rem / NGR;
        int i   = rem - p * NGR;
        int m   = (i < NGR/2) ? i : i - NGR;
        const float* rp = r + (p0 + p) * 3;
        float u = d_B[3*d]*rp[0] + d_B[3*d+1]*rp[1] + d_B[3*d+2]*rp[2];
        float sv, cv;
        sincosf((float)m * u, &sv, &cv);
        se[(d * NTILE + p) * NGR + i] = make_float2(cv, sv);
    }
    if (tid == 0) {
        asm volatile("mbarrier.init.shared.b64 [%0], %1;" :: "r"(mbar0), "r"(1u) : "memory");
        asm volatile("mbarrier.init.shared.b64 [%0], %1;" :: "r"(mbar1), "r"(1u) : "memory");
    }
    __syncthreads();

    // prologue: issue A(0) copy; generate B(0); sync
    if (tid == 0) {
        asm volatile("mbarrier.arrive.expect_tx.shared.b64 _, [%0], %1;"
                     :: "r"(mbar0), "r"((uint32_t)STG_BYTES) : "memory");
        asm volatile("cp.async.bulk.shared::cluster.global.mbarrier::complete_tx::bytes [%0], [%1], %2, [%3];"
                     :: "r"(sb), "l"((const char*)d_A2), "r"((uint32_t)STG_BYTES), "r"(mbar0) : "memory");
    }
    bgen(smem, se, 0, wid, lane);
    __syncthreads();

    // accumulators (Karatsuba): S1=cr*pr, S2=ci*pi, S3=cs*ps
    float S1[2][4][4], S2[2][4][4], S3[2][4][4];
    #pragma unroll
    for (int mt = 0; mt < 2; mt++)
        #pragma unroll
        for (int nt = 0; nt < 4; nt++)
            #pragma unroll
            for (int q = 0; q < 4; q++) { S1[mt][nt][q]=0.f; S2[mt][nt][q]=0.f; S3[mt][nt][q]=0.f; }

    // per-thread ldmatrix row offsets
    const uint32_t aRowOff = (lane & 15) * 80 + (lane >> 4) * 16;
    const uint32_t bRowOff = (((lane >> 4) & 1) * 8 + (lane & 7)) * 80 + ((lane >> 3) & 1) * 16;
    const int m0 = (wid & 3) * 32;    // 4 m-warps
    const int n0 = (wid >> 2) * 32;   // 2 n-warps
    const uint32_t amBase = (uint32_t)m0 * 80 + aRowOff;
    const uint32_t bnBase = (uint32_t)n0 * 80 + bRowOff;

    for (int s = 0; s < NSTAGE; s++) {
        const int cur = s & 1;
        const uint32_t aBuf = sb + cur * STG_BYTES;
        const uint32_t bBuf = sb + B_OFF + cur * BS_BUF;

        // ---- issue bulk copy for stage s+1 into the other A buffer
        //      (freed by the __syncthreads at the end of stage s-1) ----
        if (tid == 0 && s + 1 < NSTAGE) {
            uint32_t nb = (s + 1) & 1;
            uint32_t mb = nb ? mbar1 : mbar0;
            asm volatile("mbarrier.arrive.expect_tx.shared.b64 _, [%0], %1;"
                         :: "r"(mb), "r"((uint32_t)STG_BYTES) : "memory");
            const char* src = (const char*)d_A2 + (size_t)(s + 1) * STG_BYTES;
            asm volatile("cp.async.bulk.shared::cluster.global.mbarrier::complete_tx::bytes [%0], [%1], %2, [%3];"
                         :: "r"(sb + nb * STG_BYTES), "l"(src), "r"((uint32_t)STG_BYTES), "r"(mb) : "memory");
        }

        // ---- wait for A(s), then issue the MMA burst ----
        MBAR_WAIT(cur ? mbar1 : mbar0, (uint32_t)((s >> 1) & 1));

        #pragma unroll
        for (int k16 = 0; k16 < 2; k16++) {
            uint32_t kb = k16 * 32;
            mma_set(S1, aBuf + 0*AS_VAR + amBase + kb, aBuf + 1*AS_VAR + amBase + kb,
                        bBuf + 0*BS_VAR + bnBase + kb, bBuf + 1*BS_VAR + bnBase + kb);
            mma_set(S2, aBuf + 2*AS_VAR + amBase + kb, aBuf + 3*AS_VAR + amBase + kb,
                        bBuf + 2*BS_VAR + bnBase + kb, bBuf + 3*BS_VAR + bnBase + kb);
            mma_set(S3, aBuf + 4*AS_VAR + amBase + kb, aBuf + 5*AS_VAR + amBase + kb,
                        bBuf + 4*BS_VAR + bnBase + kb, bBuf + 5*BS_VAR + bnBase + kb);
        }

        // ---- generate B(s+1) behind the MMA burst (writes buf cur^1,
        //      last read by MMA(s-1), done at the previous sync) ----
        if (s + 1 < NSTAGE)
            bgen(smem, se, s + 1, wid, lane);

        __syncthreads();   // MMA(s) done + B(s+1) visible everywhere
    }

    // ---- epilogue: Re = S1-S2, Im = S3-S1-S2; rotate by k, scale, store ----
    const bool cplx = (out_elems >= 2 * NB * NPTS);
    const float scale = d_scale;
    #pragma unroll
    for (int mt = 0; mt < 2; mt++) {
        #pragma unroll
        for (int nt = 0; nt < 4; nt++) {
            #pragma unroll
            for (int q = 0; q < 4; q++) {
                float v1 = S1[mt][nt][q], v2 = S2[mt][nt][q], v3 = S3[mt][nt][q];
                float Re = v1 - v2;
                float Im = v3 - v1 - v2;
                int b = m0 + mt * 16 + (lane >> 2) + (q >> 1) * 8;
                int p = p0 + n0 + nt * 8 + (lane & 3) * 2 + (q & 1);
                int kq = (b >> 4) & 3;
                const float* rp = r + p * 3;
                float ang = kg[3*kq]*rp[0] + kg[3*kq+1]*rp[1] + kg[3*kq+2]*rp[2];
                float sv, cv;
                sincosf(ang, &sv, &cv);
                float ore = (Re * cv - Im * sv) * scale;
                float oim = (Re * sv + Im * cv) * scale;
                size_t idx = (size_t)b * NPTS + p;
                if (cplx) ((float2*)out)[idx] = make_float2(ore, oim);
                else      out[idx] = ore;
            }
        }
    }
}

extern "C" void kernel_launch(void* const* d_in, const int* in_sizes, int n_in,
                              void* d_out, int out_size) {
    const float* A   = nullptr;
    const float* kg  = nullptr;
    const float* r   = nullptr;
    const float* cre = nullptr;
    const float* cim = nullptr;
    for (int i = 0; i < n_in; i++) {
        const float* p = (const float*)d_in[i];
        long long sz = in_sizes[i];
        if (sz == 9 || sz == 36)               A = p;
        else if (sz == 12 || sz == 48)         kg = p;
        else if (sz == 24000 || sz == 96000)   r = p;
        else if (sz == (long long)NB * NG || sz == (long long)NB * NG * 4) {
            if (!cre) cre = p; else cim = p;
        }
    }
    if (!A || !kg || !r || !cre || !cim) {
        if (n_in >= 5) {
            A   = (const float*)d_in[0];
            kg  = (const float*)d_in[1];
            cre = (const float*)d_in[2];
            cim = (const float*)d_in[3];
            r   = (const float*)d_in[4];
        } else {
            return;
        }
    }

    static bool attr_set = false;
    if (!attr_set) {
        cudaFuncSetAttribute(mma_kernel, cudaFuncAttributeMaxDynamicSharedMemorySize, SM_TOTAL);
        attr_set = true;
    }

    prep_kernel<<<NB, 256>>>(cre, cim, A);
    mma_kernel<<<NCTA, NT, SM_TOTAL>>>(r, kg, (float*)d_out, out_size);
}

// round 14
// speedup vs baseline: 1.7415x; 1.4439x over previous
#include <cuda_runtime.h>
#include <cuda_fp16.h>
#include <math.h>
#include <stdint.h>

#define NB     128     // batches
#define NG     8000    // plane waves (20^3)
#define NPTS   8000    // points
#define NGR    20      // grid per dim
#define KC     32      // K per stage
#define NSTAGE 250     // NG / KC
#define NTILE  64      // points per CTA
#define NCTA   125     // NPTS / NTILE
#define NT     256     // threads (8 warps, 4m x 2n grid: m32 x n32 per warp)

// A stage chunk: 6 variants x 128 rows x 80B (64B data + 16B pad) = 61440 B
#define STG_BYTES 61440
#define AS_VAR    10240
#define B_OFF     122880                     // after 2 A buffers
#define BS_BUF    15360                      // 3 variants x 64 rows x 80B
#define BS_VAR    5120
#define SE_OFF    153600                     // 3 x 64 x 20 x float2 = 30720
#define MB_OFF    184320                     // 2 mbarriers
#define SM_TOTAL  184352

__device__ float d_B[9];
__device__ float d_scale;
// stage-major, ldmatrix-ready (80B rows, pad zeroed), fp16:
// v: 0 crh 1 crl 2 cih 3 cil 4 csh 5 csl   (cs = cr + ci; hi/lo fp16 split)
__device__ __align__(128) __half d_A2[(size_t)NSTAGE * 6 * NB * 40];  // 15.36 MB

// ---------------- helpers ----------------
__device__ __forceinline__ uint32_t smem_u32(const void* p) {
    uint32_t a;
    asm("{ .reg .u64 t; cvta.to.shared.u64 t, %1; cvt.u32.u64 %0, t; }" : "=r"(a) : "l"(p));
    return a;
}
__device__ __forceinline__ float2 cmul(float2 a, float2 b) {
    return make_float2(a.x*b.x - a.y*b.y, a.x*b.y + a.y*b.x);
}

#define MMAF16(d, a, b0, b1) \
    asm volatile("mma.sync.aligned.m16n8k16.row.col.f32.f16.f16.f32 " \
        "{%0,%1,%2,%3}, {%4,%5,%6,%7}, {%8,%9}, {%0,%1,%2,%3};" \
        : "+f"((d)[0]), "+f"((d)[1]), "+f"((d)[2]), "+f"((d)[3]) \
        : "r"((a)[0]), "r"((a)[1]), "r"((a)[2]), "r"((a)[3]), "r"(b0), "r"(b1))

#define LDSM_X4(r, addr) \
    asm volatile("ldmatrix.sync.aligned.m8n8.x4.shared.b16 {%0,%1,%2,%3}, [%4];" \
        : "=r"((r)[0]), "=r"((r)[1]), "=r"((r)[2]), "=r"((r)[3]) : "r"(addr))

#define MBAR_WAIT(mbar, parity) do { \
    uint32_t _m = (mbar); uint32_t _p = (parity); uint32_t _d; \
    asm volatile("{ .reg .pred p; mbarrier.try_wait.parity.acquire.cta.shared::cta.b64 p, [%1], %2; selp.b32 %0, 1, 0, p; }" \
        : "=r"(_d) : "r"(_m), "r"(_p) : "memory"); \
    if (!_d) { \
        asm volatile("{ .reg .pred P1; WL_%=: mbarrier.try_wait.parity.acquire.cta.shared::cta.b64 P1, [%0], %1, 0x989680; @P1 bra.uni WD_%=; bra.uni WL_%=; WD_%=: }" \
            :: "r"(_m), "r"(_p) : "memory"); \
    } \
} while (0)

// ---------------- prep: setup (block 0) + stage-major fp16 hi/lo splits ----------------
__global__ void prep_kernel(const float* __restrict__ cre, const float* __restrict__ cim,
                            const float* __restrict__ A) {
    if (blockIdx.x == 0 && threadIdx.x == 0) {
        double a00=A[0],a01=A[1],a02=A[2];
        double a10=A[3],a11=A[4],a12=A[5];
        double a20=A[6],a21=A[7],a22=A[8];
        double c00 =  (a11*a22 - a12*a21);
        double c01 = -(a10*a22 - a12*a20);
        double c02 =  (a10*a21 - a11*a20);
        double c10 = -(a01*a22 - a02*a21);
        double c11 =  (a00*a22 - a02*a20);
        double c12 = -(a00*a21 - a01*a20);
        double c20 =  (a01*a12 - a02*a11);
        double c21 = -(a00*a12 - a02*a10);
        double c22 =  (a00*a11 - a01*a10);
        double det = a00*c00 + a01*c01 + a02*c02;
        double tp  = 6.283185307179586476925286766559;
        double s   = tp / det;
        d_B[0]=(float)(c00*s); d_B[1]=(float)(c01*s); d_B[2]=(float)(c02*s);
        d_B[3]=(float)(c10*s); d_B[4]=(float)(c11*s); d_B[5]=(float)(c12*s);
        d_B[6]=(float)(c20*s); d_B[7]=(float)(c21*s); d_B[8]=(float)(c22*s);
        d_scale = (float)(1.0 / sqrt(fabs(det)));
    }
    int b = blockIdx.x;
    for (int g = threadIdx.x; g < NG; g += 256) {
        int s  = g >> 5;
        int gl = g & 31;
        float vr = cre[(size_t)b * NG + g];
        float vi = cim[(size_t)b * NG + g];
        float vs = vr + vi;
        __half rh = __float2half(vr);
        __half rl = __float2half(vr - __half2float(rh));
        __half ih = __float2half(vi);
        __half il = __float2half(vi - __half2float(ih));
        __half sh = __float2half(vs);
        __half sl = __float2half(vs - __half2float(sh));
        size_t base = ((size_t)s * 6 * NB + b) * 40 + gl;
        d_A2[base + (size_t)0 * NB * 40] = rh;
        d_A2[base + (size_t)1 * NB * 40] = rl;
        d_A2[base + (size_t)2 * NB * 40] = ih;
        d_A2[base + (size_t)3 * NB * 40] = il;
        d_A2[base + (size_t)4 * NB * 40] = sh;
        d_A2[base + (size_t)5 * NB * 40] = sl;
    }
    // zero the 16B row padding (deterministic every call)
    __half z = __float2half(0.0f);
    for (int t = threadIdx.x; t < NSTAGE * 6 * 8; t += 256) {
        int s = t / 48;
        int rem = t - s * 48;
        int v = rem >> 3;
        int q = rem & 7;
        d_A2[(((size_t)s * 6 + v) * NB + b) * 40 + 32 + q] = z;
    }
}

// ---------------- B phase generation (hi-only fp16, 3 variants) ----------------
__device__ __forceinline__ void bgen(char* smem, const float2* se, int s,
                                     int wid, int lane)
{
    int gl = lane;
    int g  = s * KC + gl;
    int i1 = g / 400;
    int i2 = (g / 20) % 20;
    int i3 = g % 20;
    char* bptr = smem + B_OFF + (s & 1) * BS_BUF;
    #pragma unroll
    for (int pi = 0; pi < 8; pi++) {
        int p = wid * 8 + pi;
        float2 e1 = se[(0 * NTILE + p) * NGR + i1];
        float2 e2 = se[(1 * NTILE + p) * NGR + i2];
        float2 e3 = se[(2 * NTILE + p) * NGR + i3];
        float2 ph = cmul(cmul(e1, e2), e3);
        __half prh = __float2half(ph.x);
        __half pih = __float2half(ph.y);
        __half psh = __float2half(ph.x + ph.y);
        uint32_t off = (uint32_t)p * 80 + gl * 2;
        *(__half*)(bptr + 0 * BS_VAR + off) = prh;
        *(__half*)(bptr + 1 * BS_VAR + off) = pih;
        *(__half*)(bptr + 2 * BS_VAR + off) = psh;
    }
}

// ---------------- mma block: m32 x n32 x k16, A hi+lo x B hi (2 products) ----------------
__device__ __forceinline__ void mma_set2(
    float S[2][4][4], uint32_t aH, uint32_t aL, uint32_t bH)
{
    uint32_t ah[2][4], al[2][4], bh[2][4];
    #pragma unroll
    for (int mt = 0; mt < 2; mt++) {
        LDSM_X4(ah[mt], aH + mt * 16 * 80);
        LDSM_X4(al[mt], aL + mt * 16 * 80);
    }
    #pragma unroll
    for (int np = 0; np < 2; np++)
        LDSM_X4(bh[np], bH + np * 16 * 80);
    #pragma unroll
    for (int mt = 0; mt < 2; mt++) {
        #pragma unroll
        for (int nt = 0; nt < 4; nt++) {
            int np = nt >> 1, q = (nt & 1) * 2;
            MMAF16(S[mt][nt], ah[mt], bh[np][q], bh[np][q+1]);   // hi*hi
            MMAF16(S[mt][nt], al[mt], bh[np][q], bh[np][q+1]);   // lo*hi
        }
    }
}

// ---------------- main kernel ----------------
__global__ void __launch_bounds__(NT, 1)
mma_kernel(const float* __restrict__ r, const float* __restrict__ kg,
           float* __restrict__ out, int out_elems)
{
    extern __shared__ char smem[];
    uint32_t sb = smem_u32(smem);
    const int tid  = threadIdx.x;
    const int wid  = tid >> 5;
    const int lane = tid & 31;
    const int p0   = blockIdx.x * NTILE;
    const uint32_t mbar0 = sb + MB_OFF;
    const uint32_t mbar1 = sb + MB_OFF + 8;

    // e tables: se[(d*64+p)*20+i] = exp(i * m(i) * (B_d . r_p))
    float2* se = (float2*)(smem + SE_OFF);
    for (int t = tid; t < 3 * NTILE * NGR; t += NT) {
        int d   = t / (NTILE * NGR);
        int rem = t - d * NTILE * NGR;
        int p   = rem / NGR;
        int i   = rem - p * NGR;
        int m   = (i < NGR/2) ? i : i - NGR;
        const float* rp = r + (p0 + p) * 3;
        float u = d_B[3*d]*rp[0] + d_B[3*d+1]*rp[1] + d_B[3*d+2]*rp[2];
        float sv, cv;
        sincosf((float)m * u, &sv, &cv);
        se[(d * NTILE + p) * NGR + i] = make_float2(cv, sv);
    }
    if (tid == 0) {
        asm volatile("mbarrier.init.shared.b64 [%0], %1;" :: "r"(mbar0), "r"(1u) : "memory");
        asm volatile("mbarrier.init.shared.b64 [%0], %1;" :: "r"(mbar1), "r"(1u) : "memory");
    }
    __syncthreads();

    // prologue: issue A(0) copy; generate B(0); sync
    if (tid == 0) {
        asm volatile("mbarrier.arrive.expect_tx.shared.b64 _, [%0], %1;"
                     :: "r"(mbar0), "r"((uint32_t)STG_BYTES) : "memory");
        asm volatile("cp.async.bulk.shared::cluster.global.mbarrier::complete_tx::bytes [%0], [%1], %2, [%3];"
                     :: "r"(sb), "l"((const char*)d_A2), "r"((uint32_t)STG_BYTES), "r"(mbar0) : "memory");
    }
    bgen(smem, se, 0, wid, lane);
    __syncthreads();

    // accumulators (Karatsuba): S1=cr*pr, S2=ci*pi, S3=cs*ps
    float S1[2][4][4], S2[2][4][4], S3[2][4][4];
    #pragma unroll
    for (int mt = 0; mt < 2; mt++)
        #pragma unroll
        for (int nt = 0; nt < 4; nt++)
            #pragma unroll
            for (int q = 0; q < 4; q++) { S1[mt][nt][q]=0.f; S2[mt][nt][q]=0.f; S3[mt][nt][q]=0.f; }

    // per-thread ldmatrix row offsets
    const uint32_t aRowOff = (lane & 15) * 80 + (lane >> 4) * 16;
    const uint32_t bRowOff = (((lane >> 4) & 1) * 8 + (lane & 7)) * 80 + ((lane >> 3) & 1) * 16;
    const int m0 = (wid & 3) * 32;    // 4 m-warps
    const int n0 = (wid >> 2) * 32;   // 2 n-warps
    const uint32_t amBase = (uint32_t)m0 * 80 + aRowOff;
    const uint32_t bnBase = (uint32_t)n0 * 80 + bRowOff;

    for (int s = 0; s < NSTAGE; s++) {
        const int cur = s & 1;
        const uint32_t aBuf = sb + cur * STG_BYTES;
        const uint32_t bBuf = sb + B_OFF + cur * BS_BUF;

        // ---- issue bulk copy for stage s+1 into the other A buffer ----
        if (tid == 0 && s + 1 < NSTAGE) {
            uint32_t nb = (s + 1) & 1;
            uint32_t mb = nb ? mbar1 : mbar0;
            asm volatile("mbarrier.arrive.expect_tx.shared.b64 _, [%0], %1;"
                         :: "r"(mb), "r"((uint32_t)STG_BYTES) : "memory");
            const char* src = (const char*)d_A2 + (size_t)(s + 1) * STG_BYTES;
            asm volatile("cp.async.bulk.shared::cluster.global.mbarrier::complete_tx::bytes [%0], [%1], %2, [%3];"
                         :: "r"(sb + nb * STG_BYTES), "l"(src), "r"((uint32_t)STG_BYTES), "r"(mb) : "memory");
        }

        // ---- wait for A(s), then issue the MMA burst ----
        MBAR_WAIT(cur ? mbar1 : mbar0, (uint32_t)((s >> 1) & 1));

        #pragma unroll
        for (int k16 = 0; k16 < 2; k16++) {
            uint32_t kb = k16 * 32;
            mma_set2(S1, aBuf + 0*AS_VAR + amBase + kb, aBuf + 1*AS_VAR + amBase + kb,
                         bBuf + 0*BS_VAR + bnBase + kb);
            mma_set2(S2, aBuf + 2*AS_VAR + amBase + kb, aBuf + 3*AS_VAR + amBase + kb,
                         bBuf + 1*BS_VAR + bnBase + kb);
            mma_set2(S3, aBuf + 4*AS_VAR + amBase + kb, aBuf + 5*AS_VAR + amBase + kb,
                         bBuf + 2*BS_VAR + bnBase + kb);
        }

        // ---- generate B(s+1) behind the MMA burst ----
        if (s + 1 < NSTAGE)
            bgen(smem, se, s + 1, wid, lane);

        __syncthreads();   // MMA(s) done + B(s+1) visible everywhere
    }

    // ---- epilogue: Re = S1-S2, Im = S3-S1-S2; rotate by k, scale, store ----
    const bool cplx = (out_elems >= 2 * NB * NPTS);
    const float scale = d_scale;
    #pragma unroll
    for (int mt = 0; mt < 2; mt++) {
        #pragma unroll
        for (int nt = 0; nt < 4; nt++) {
            #pragma unroll
            for (int q = 0; q < 4; q++) {
                float v1 = S1[mt][nt][q], v2 = S2[mt][nt][q], v3 = S3[mt][nt][q];
                float Re = v1 - v2;
                float Im = v3 - v1 - v2;
                int b = m0 + mt * 16 + (lane >> 2) + (q >> 1) * 8;
                int p = p0 + n0 + nt * 8 + (lane & 3) * 2 + (q & 1);
                int kq = (b >> 4) & 3;
                const float* rp = r + p * 3;
                float ang = kg[3*kq]*rp[0] + kg[3*kq+1]*rp[1] + kg[3*kq+2]*rp[2];
                float sv, cv;
                sincosf(ang, &sv, &cv);
                float ore = (Re * cv - Im * sv) * scale;
                float oim = (Re * sv + Im * cv) * scale;
                size_t idx = (size_t)b * NPTS + p;
                if (cplx) ((float2*)out)[idx] = make_float2(ore, oim);
                else      out[idx] = ore;
            }
        }
    }
}

extern "C" void kernel_launch(void* const* d_in, const int* in_sizes, int n_in,
                              void* d_out, int out_size) {
    const float* A   = nullptr;
    const float* kg  = nullptr;
    const float* r   = nullptr;
    const float* cre = nullptr;
    const float* cim = nullptr;
    for (int i = 0; i < n_in; i++) {
        const float* p = (const float*)d_in[i];
        long long sz = in_sizes[i];
        if (sz == 9 || sz == 36)               A = p;
        else if (sz == 12 || sz == 48)         kg = p;
        else if (sz == 24000 || sz == 96000)   r = p;
        else if (sz == (long long)NB * NG || sz == (long long)NB * NG * 4) {
            if (!cre) cre = p; else cim = p;
        }
    }
    if (!A || !kg || !r || !cre || !cim) {
        if (n_in >= 5) {
            A   = (const float*)d_in[0];
            kg  = (const float*)d_in[1];
            cre = (const float*)d_in[2];
            cim = (const float*)d_in[3];
            r   = (const float*)d_in[4];
        } else {
            return;
        }
    }

    static bool attr_set = false;
    if (!attr_set) {
        cudaFuncSetAttribute(mma_kernel, cudaFuncAttributeMaxDynamicSharedMemorySize, SM_TOTAL);
        attr_set = true;
    }

    prep_kernel<<<NB, 256>>>(cre, cim, A);
    mma_kernel<<<NCTA, NT, SM_TOTAL>>>(r, kg, (float*)d_out, out_size);
}

// round 15
// speedup vs baseline: 2.3089x; 1.3258x over previous
#include <cuda_runtime.h>
#include <cuda_fp16.h>
#include <math.h>
#include <stdint.h>

#define NB     128     // batches
#define NG     8000    // plane waves (20^3)
#define NPTS   8000    // points
#define NGR    20      // grid per dim
#define KC     32      // K per stage
#define NSTAGE 250     // NG / KC
#define NTILE  32      // points per CTA
#define NCTA   250     // NPTS / NTILE
#define NT     256     // threads (8 warps, 4m x 2n grid: m32 x n16 per warp)

// A stage chunk: 3 variants x 128 rows x 80B (64B data + 16B pad) = 30720 B
#define STG_BYTES 30720
#define AS_VAR    10240
#define B_OFF     61440                      // after 2 A buffers
#define BS_BUF    7680                       // 3 variants x 32 rows x 80B
#define BS_VAR    2560
#define SE_OFF    76800                      // 3 x 32 x 20 x float2 = 15360
#define MB_OFF    92160                      // 2 mbarriers
#define SM_TOTAL  92192

__device__ float d_B[9];
__device__ float d_scale;
// stage-major, ldmatrix-ready (80B rows, pad zeroed), fp16 hi-only:
// v: 0 crh 1 cih 2 csh   (cs = cr + ci)
__device__ __align__(128) __half d_A2[(size_t)NSTAGE * 3 * NB * 40];  // 7.68 MB

// ---------------- helpers ----------------
__device__ __forceinline__ uint32_t smem_u32(const void* p) {
    uint32_t a;
    asm("{ .reg .u64 t; cvta.to.shared.u64 t, %1; cvt.u32.u64 %0, t; }" : "=r"(a) : "l"(p));
    return a;
}
__device__ __forceinline__ float2 cmul(float2 a, float2 b) {
    return make_float2(a.x*b.x - a.y*b.y, a.x*b.y + a.y*b.x);
}

#define MMAF16(d, a, b0, b1) \
    asm volatile("mma.sync.aligned.m16n8k16.row.col.f32.f16.f16.f32 " \
        "{%0,%1,%2,%3}, {%4,%5,%6,%7}, {%8,%9}, {%0,%1,%2,%3};" \
        : "+f"((d)[0]), "+f"((d)[1]), "+f"((d)[2]), "+f"((d)[3]) \
        : "r"((a)[0]), "r"((a)[1]), "r"((a)[2]), "r"((a)[3]), "r"(b0), "r"(b1))

#define LDSM_X4(r, addr) \
    asm volatile("ldmatrix.sync.aligned.m8n8.x4.shared.b16 {%0,%1,%2,%3}, [%4];" \
        : "=r"((r)[0]), "=r"((r)[1]), "=r"((r)[2]), "=r"((r)[3]) : "r"(addr))

#define MBAR_WAIT(mbar, parity) do { \
    uint32_t _m = (mbar); uint32_t _p = (parity); uint32_t _d; \
    asm volatile("{ .reg .pred p; mbarrier.try_wait.parity.acquire.cta.shared::cta.b64 p, [%1], %2; selp.b32 %0, 1, 0, p; }" \
        : "=r"(_d) : "r"(_m), "r"(_p) : "memory"); \
    if (!_d) { \
        asm volatile("{ .reg .pred P1; WL_%=: mbarrier.try_wait.parity.acquire.cta.shared::cta.b64 P1, [%0], %1, 0x989680; @P1 bra.uni WD_%=; bra.uni WL_%=; WD_%=: }" \
            :: "r"(_m), "r"(_p) : "memory"); \
    } \
} while (0)

// ---------------- prep: setup (block 0) + stage-major fp16 hi splits ----------------
__global__ void prep_kernel(const float* __restrict__ cre, const float* __restrict__ cim,
                            const float* __restrict__ A) {
    if (blockIdx.x == 0 && threadIdx.x == 0) {
        double a00=A[0],a01=A[1],a02=A[2];
        double a10=A[3],a11=A[4],a12=A[5];
        double a20=A[6],a21=A[7],a22=A[8];
        double c00 =  (a11*a22 - a12*a21);
        double c01 = -(a10*a22 - a12*a20);
        double c02 =  (a10*a21 - a11*a20);
        double c10 = -(a01*a22 - a02*a21);
        double c11 =  (a00*a22 - a02*a20);
        double c12 = -(a00*a21 - a01*a20);
        double c20 =  (a01*a12 - a02*a11);
        double c21 = -(a00*a12 - a02*a10);
        double c22 =  (a00*a11 - a01*a10);
        double det = a00*c00 + a01*c01 + a02*c02;
        double tp  = 6.283185307179586476925286766559;
        double s   = tp / det;
        d_B[0]=(float)(c00*s); d_B[1]=(float)(c01*s); d_B[2]=(float)(c02*s);
        d_B[3]=(float)(c10*s); d_B[4]=(float)(c11*s); d_B[5]=(float)(c12*s);
        d_B[6]=(float)(c20*s); d_B[7]=(float)(c21*s); d_B[8]=(float)(c22*s);
        d_scale = (float)(1.0 / sqrt(fabs(det)));
    }
    int b = blockIdx.x;
    for (int g = threadIdx.x; g < NG; g += 256) {
        int s  = g >> 5;
        int gl = g & 31;
        float vr = cre[(size_t)b * NG + g];
        float vi = cim[(size_t)b * NG + g];
        size_t base = ((size_t)s * 3 * NB + b) * 40 + gl;
        d_A2[base + (size_t)0 * NB * 40] = __float2half(vr);
        d_A2[base + (size_t)1 * NB * 40] = __float2half(vi);
        d_A2[base + (size_t)2 * NB * 40] = __float2half(vr + vi);
    }
    // zero the 16B row padding (deterministic every call)
    __half z = __float2half(0.0f);
    for (int t = threadIdx.x; t < NSTAGE * 3 * 8; t += 256) {
        int s = t / 24;
        int rem = t - s * 24;
        int v = rem >> 3;
        int q = rem & 7;
        d_A2[(((size_t)s * 3 + v) * NB + b) * 40 + 32 + q] = z;
    }
}

// ---------------- B phase generation (hi-only fp16, 3 variants, 4 pts/warp) ----------------
__device__ __forceinline__ void bgen(char* smem, const float2* se, int s,
                                     int wid, int lane)
{
    int gl = lane;
    int g  = s * KC + gl;
    int i1 = g / 400;
    int i2 = (g / 20) % 20;
    int i3 = g % 20;
    char* bptr = smem + B_OFF + (s & 1) * BS_BUF;
    #pragma unroll
    for (int pi = 0; pi < 4; pi++) {
        int p = wid * 4 + pi;
        float2 e1 = se[(0 * NTILE + p) * NGR + i1];
        float2 e2 = se[(1 * NTILE + p) * NGR + i2];
        float2 e3 = se[(2 * NTILE + p) * NGR + i3];
        float2 ph = cmul(cmul(e1, e2), e3);
        uint32_t off = (uint32_t)p * 80 + gl * 2;
        *(__half*)(bptr + 0 * BS_VAR + off) = __float2half(ph.x);
        *(__half*)(bptr + 1 * BS_VAR + off) = __float2half(ph.y);
        *(__half*)(bptr + 2 * BS_VAR + off) = __float2half(ph.x + ph.y);
    }
}

// ---------------- mma block: m32 x n16 x k16, single product ----------------
__device__ __forceinline__ void mma_set1(
    float S[2][2][4], uint32_t aH, uint32_t bH)
{
    uint32_t ah[2][4], bh[4];
    #pragma unroll
    for (int mt = 0; mt < 2; mt++)
        LDSM_X4(ah[mt], aH + mt * 16 * 80);
    LDSM_X4(bh, bH);
    #pragma unroll
    for (int mt = 0; mt < 2; mt++) {
        #pragma unroll
        for (int nt = 0; nt < 2; nt++) {
            int q = nt * 2;
            MMAF16(S[mt][nt], ah[mt], bh[q], bh[q+1]);
        }
    }
}

// ---------------- main kernel ----------------
__global__ void __launch_bounds__(NT, 2)
mma_kernel(const float* __restrict__ r, const float* __restrict__ kg,
           float* __restrict__ out, int out_elems)
{
    extern __shared__ char smem[];
    uint32_t sb = smem_u32(smem);
    const int tid  = threadIdx.x;
    const int wid  = tid >> 5;
    const int lane = tid & 31;
    const int p0   = blockIdx.x * NTILE;
    const uint32_t mbar0 = sb + MB_OFF;
    const uint32_t mbar1 = sb + MB_OFF + 8;

    // e tables: se[(d*32+p)*20+i] = exp(i * m(i) * (B_d . r_p))
    float2* se = (float2*)(smem + SE_OFF);
    for (int t = tid; t < 3 * NTILE * NGR; t += NT) {
        int d   = t / (NTILE * NGR);
        int rem = t - d * NTILE * NGR;
        int p   = rem / NGR;
        int i   = rem - p * NGR;
        int m   = (i < NGR/2) ? i : i - NGR;
        const float* rp = r + (p0 + p) * 3;
        float u = d_B[3*d]*rp[0] + d_B[3*d+1]*rp[1] + d_B[3*d+2]*rp[2];
        float sv, cv;
        sincosf((float)m * u, &sv, &cv);
        se[(d * NTILE + p) * NGR + i] = make_float2(cv, sv);
    }
    if (tid == 0) {
        asm volatile("mbarrier.init.shared.b64 [%0], %1;" :: "r"(mbar0), "r"(1u) : "memory");
        asm volatile("mbarrier.init.shared.b64 [%0], %1;" :: "r"(mbar1), "r"(1u) : "memory");
    }
    __syncthreads();

    // prologue: issue A(0) copy; generate B(0); sync
    if (tid == 0) {
        asm volatile("mbarrier.arrive.expect_tx.shared.b64 _, [%0], %1;"
                     :: "r"(mbar0), "r"((uint32_t)STG_BYTES) : "memory");
        asm volatile("cp.async.bulk.shared::cluster.global.mbarrier::complete_tx::bytes [%0], [%1], %2, [%3];"
                     :: "r"(sb), "l"((const char*)d_A2), "r"((uint32_t)STG_BYTES), "r"(mbar0) : "memory");
    }
    bgen(smem, se, 0, wid, lane);
    __syncthreads();

    // accumulators (Karatsuba): S1=cr*pr, S2=ci*pi, S3=cs*ps
    float S1[2][2][4], S2[2][2][4], S3[2][2][4];
    #pragma unroll
    for (int mt = 0; mt < 2; mt++)
        #pragma unroll
        for (int nt = 0; nt < 2; nt++)
            #pragma unroll
            for (int q = 0; q < 4; q++) { S1[mt][nt][q]=0.f; S2[mt][nt][q]=0.f; S3[mt][nt][q]=0.f; }

    // per-thread ldmatrix row offsets
    const uint32_t aRowOff = (lane & 15) * 80 + (lane >> 4) * 16;
    const uint32_t bRowOff = (((lane >> 4) & 1) * 8 + (lane & 7)) * 80 + ((lane >> 3) & 1) * 16;
    const int m0 = (wid & 3) * 32;    // 4 m-warps
    const int n0 = (wid >> 2) * 16;   // 2 n-warps
    const uint32_t amBase = (uint32_t)m0 * 80 + aRowOff;
    const uint32_t bnBase = (uint32_t)n0 * 80 + bRowOff;

    for (int s = 0; s < NSTAGE; s++) {
        const int cur = s & 1;
        const uint32_t aBuf = sb + cur * STG_BYTES;
        const uint32_t bBuf = sb + B_OFF + cur * BS_BUF;

        // ---- issue bulk copy for stage s+1 into the other A buffer ----
        if (tid == 0 && s + 1 < NSTAGE) {
            uint32_t nb = (s + 1) & 1;
            uint32_t mb = nb ? mbar1 : mbar0;
            asm volatile("mbarrier.arrive.expect_tx.shared.b64 _, [%0], %1;"
                         :: "r"(mb), "r"((uint32_t)STG_BYTES) : "memory");
            const char* src = (const char*)d_A2 + (size_t)(s + 1) * STG_BYTES;
            asm volatile("cp.async.bulk.shared::cluster.global.mbarrier::complete_tx::bytes [%0], [%1], %2, [%3];"
                         :: "r"(sb + nb * STG_BYTES), "l"(src), "r"((uint32_t)STG_BYTES), "r"(mb) : "memory");
        }

        // ---- wait for A(s), then issue the MMA burst ----
        MBAR_WAIT(cur ? mbar1 : mbar0, (uint32_t)((s >> 1) & 1));

        #pragma unroll
        for (int k16 = 0; k16 < 2; k16++) {
            uint32_t kb = k16 * 32;
            mma_set1(S1, aBuf + 0*AS_VAR + amBase + kb, bBuf + 0*BS_VAR + bnBase + kb);
            mma_set1(S2, aBuf + 1*AS_VAR + amBase + kb, bBuf + 1*BS_VAR + bnBase + kb);
            mma_set1(S3, aBuf + 2*AS_VAR + amBase + kb, bBuf + 2*BS_VAR + bnBase + kb);
        }

        // ---- generate B(s+1) behind the MMA burst ----
        if (s + 1 < NSTAGE)
            bgen(smem, se, s + 1, wid, lane);

        __syncthreads();   // MMA(s) done + B(s+1) visible everywhere
    }

    // ---- epilogue: Re = S1-S2, Im = S3-S1-S2; rotate by k, scale, store ----
    const bool cplx = (out_elems >= 2 * NB * NPTS);
    const float scale = d_scale;
    #pragma unroll
    for (int mt = 0; mt < 2; mt++) {
        #pragma unroll
        for (int nt = 0; nt < 2; nt++) {
            #pragma unroll
            for (int q = 0; q < 4; q++) {
                float v1 = S1[mt][nt][q], v2 = S2[mt][nt][q], v3 = S3[mt][nt][q];
                float Re = v1 - v2;
                float Im = v3 - v1 - v2;
                int b = m0 + mt * 16 + (lane >> 2) + (q >> 1) * 8;
                int p = p0 + n0 + nt * 8 + (lane & 3) * 2 + (q & 1);
                int kq = (b >> 4) & 3;
                const float* rp = r + p * 3;
                float ang = kg[3*kq]*rp[0] + kg[3*kq+1]*rp[1] + kg[3*kq+2]*rp[2];
                float sv, cv;
                sincosf(ang, &sv, &cv);
                float ore = (Re * cv - Im * sv) * scale;
                float oim = (Re * sv + Im * cv) * scale;
                size_t idx = (size_t)b * NPTS + p;
                if (cplx) ((float2*)out)[idx] = make_float2(ore, oim);
                else      out[idx] = ore;
            }
        }
    }
}

extern "C" void kernel_launch(void* const* d_in, const int* in_sizes, int n_in,
                              void* d_out, int out_size) {
    const float* A   = nullptr;
    const float* kg  = nullptr;
    const float* r   = nullptr;
    const float* cre = nullptr;
    const float* cim = nullptr;
    for (int i = 0; i < n_in; i++) {
        const float* p = (const float*)d_in[i];
        long long sz = in_sizes[i];
        if (sz == 9 || sz == 36)               A = p;
        else if (sz == 12 || sz == 48)         kg = p;
        else if (sz == 24000 || sz == 96000)   r = p;
        else if (sz == (long long)NB * NG || sz == (long long)NB * NG * 4) {
            if (!cre) cre = p; else cim = p;
        }
    }
    if (!A || !kg || !r || !cre || !cim) {
        if (n_in >= 5) {
            A   = (const float*)d_in[0];
            kg  = (const float*)d_in[1];
            cre = (const float*)d_in[2];
            cim = (const float*)d_in[3];
            r   = (const float*)d_in[4];
        } else {
            return;
        }
    }

    static bool attr_set = false;
    if (!attr_set) {
        cudaFuncSetAttribute(mma_kernel, cudaFuncAttributeMaxDynamicSharedMemorySize, SM_TOTAL);
        attr_set = true;
    }

    prep_kernel<<<NB, 256>>>(cre, cim, A);
    mma_kernel<<<NCTA, NT, SM_TOTAL>>>(r, kg, (float*)d_out, out_size);
}

// round 16
// speedup vs baseline: 2.5555x; 1.1068x over previous
#include <cuda_runtime.h>
#include <cuda_fp16.h>
#include <math.h>
#include <stdint.h>

#define NB     128     // batches
#define NG     8000    // plane waves (20^3)
#define NPTS   8000    // points
#define NGR    20      // grid per dim
#define KC     32      // K per stage
#define NSTAGE 250     // NG / KC
#define NTILE  32      // points per CTA
#define NCTA   250     // NPTS / NTILE
#define NT     256     // threads (8 warps, 4m x 2n grid: m32 x n16 per warp)

// A stage chunk: 2 variants x 128 rows x 80B (64B data + 16B pad) = 20480 B
#define STG_BYTES 20480
#define AS_VAR    10240
#define B_OFF     40960                      // after 2 A buffers
#define BS_BUF    5120                       // 2 variants x 32 rows x 80B
#define BS_VAR    2560
#define SE_OFF    51200                      // 3 x 32 x 20 x float2 = 15360
#define MB_OFF    66560                      // 2 mbarriers
#define SM_TOTAL  66592

__device__ float d_B[9];
__device__ float d_scale;
// stage-major, ldmatrix-ready (80B rows, pad zeroed), fp16 hi-only:
// v: 0 cr  1 ci
__device__ __align__(128) __half d_A2[(size_t)NSTAGE * 2 * NB * 40];  // 5.12 MB

// ---------------- helpers ----------------
__device__ __forceinline__ uint32_t smem_u32(const void* p) {
    uint32_t a;
    asm("{ .reg .u64 t; cvta.to.shared.u64 t, %1; cvt.u32.u64 %0, t; }" : "=r"(a) : "l"(p));
    return a;
}
__device__ __forceinline__ float2 cmul(float2 a, float2 b) {
    return make_float2(a.x*b.x - a.y*b.y, a.x*b.y + a.y*b.x);
}

#define MMAF16(d, a, b0, b1) \
    asm volatile("mma.sync.aligned.m16n8k16.row.col.f32.f16.f16.f32 " \
        "{%0,%1,%2,%3}, {%4,%5,%6,%7}, {%8,%9}, {%0,%1,%2,%3};" \
        : "+f"((d)[0]), "+f"((d)[1]), "+f"((d)[2]), "+f"((d)[3]) \
        : "r"((a)[0]), "r"((a)[1]), "r"((a)[2]), "r"((a)[3]), "r"(b0), "r"(b1))

#define LDSM_X4(r, addr) \
    asm volatile("ldmatrix.sync.aligned.m8n8.x4.shared.b16 {%0,%1,%2,%3}, [%4];" \
        : "=r"((r)[0]), "=r"((r)[1]), "=r"((r)[2]), "=r"((r)[3]) : "r"(addr))

#define MBAR_WAIT(mbar, parity) do { \
    uint32_t _m = (mbar); uint32_t _p = (parity); uint32_t _d; \
    asm volatile("{ .reg .pred p; mbarrier.try_wait.parity.acquire.cta.shared::cta.b64 p, [%1], %2; selp.b32 %0, 1, 0, p; }" \
        : "=r"(_d) : "r"(_m), "r"(_p) : "memory"); \
    if (!_d) { \
        asm volatile("{ .reg .pred P1; WL_%=: mbarrier.try_wait.parity.acquire.cta.shared::cta.b64 P1, [%0], %1, 0x989680; @P1 bra.uni WD_%=; bra.uni WL_%=; WD_%=: }" \
            :: "r"(_m), "r"(_p) : "memory"); \
    } \
} while (0)

// ---------------- prep: setup (block 0) + stage-major fp16 coefficients ----------------
__global__ void prep_kernel(const float* __restrict__ cre, const float* __restrict__ cim,
                            const float* __restrict__ A) {
    if (blockIdx.x == 0 && threadIdx.x == 0) {
        double a00=A[0],a01=A[1],a02=A[2];
        double a10=A[3],a11=A[4],a12=A[5];
        double a20=A[6],a21=A[7],a22=A[8];
        double c00 =  (a11*a22 - a12*a21);
        double c01 = -(a10*a22 - a12*a20);
        double c02 =  (a10*a21 - a11*a20);
        double c10 = -(a01*a22 - a02*a21);
        double c11 =  (a00*a22 - a02*a20);
        double c12 = -(a00*a21 - a01*a20);
        double c20 =  (a01*a12 - a02*a11);
        double c21 = -(a00*a12 - a02*a10);
        double c22 =  (a00*a11 - a01*a10);
        double det = a00*c00 + a01*c01 + a02*c02;
        double tp  = 6.283185307179586476925286766559;
        double s   = tp / det;
        d_B[0]=(float)(c00*s); d_B[1]=(float)(c01*s); d_B[2]=(float)(c02*s);
        d_B[3]=(float)(c10*s); d_B[4]=(float)(c11*s); d_B[5]=(float)(c12*s);
        d_B[6]=(float)(c20*s); d_B[7]=(float)(c21*s); d_B[8]=(float)(c22*s);
        d_scale = (float)(1.0 / sqrt(fabs(det)));
    }
    int b = blockIdx.x;
    for (int g = threadIdx.x; g < NG; g += 256) {
        int s  = g >> 5;
        int gl = g & 31;
        size_t base = ((size_t)s * 2 * NB + b) * 40 + gl;
        d_A2[base]                      = __float2half(cre[(size_t)b * NG + g]);
        d_A2[base + (size_t)NB * 40]    = __float2half(cim[(size_t)b * NG + g]);
    }
    // zero the 16B row padding (deterministic every call)
    __half z = __float2half(0.0f);
    for (int t = threadIdx.x; t < NSTAGE * 2 * 8; t += 256) {
        int s = t / 16;
        int rem = t - s * 16;
        int v = rem >> 3;
        int q = rem & 7;
        d_A2[(((size_t)s * 2 + v) * NB + b) * 40 + 32 + q] = z;
    }
}

// ---------------- B phase generation (hi-only fp16, 2 variants, 4 pts/warp) ----------------
__device__ __forceinline__ void bgen(char* smem, const float2* se, int s,
                                     int wid, int lane)
{
    int gl = lane;
    int g  = s * KC + gl;
    int i1 = g / 400;
    int i2 = (g / 20) % 20;
    int i3 = g % 20;
    char* bptr = smem + B_OFF + (s & 1) * BS_BUF;
    #pragma unroll
    for (int pi = 0; pi < 4; pi++) {
        int p = wid * 4 + pi;
        float2 e1 = se[(0 * NTILE + p) * NGR + i1];
        float2 e2 = se[(1 * NTILE + p) * NGR + i2];
        float2 e3 = se[(2 * NTILE + p) * NGR + i3];
        float2 ph = cmul(cmul(e1, e2), e3);
        uint32_t off = (uint32_t)p * 80 + gl * 2;
        *(__half*)(bptr + 0 * BS_VAR + off) = __float2half(ph.x);
        *(__half*)(bptr + 1 * BS_VAR + off) = __float2half(ph.y);
    }
}

// ---------------- mma block: one k16, 4 product sets with operand reuse ----------------
__device__ __forceinline__ void mma_quad(
    float Srr[2][2][4], float Sri[2][2][4], float Sir[2][2][4], float Sii[2][2][4],
    uint32_t aCr, uint32_t aCi, uint32_t bPr, uint32_t bPi)
{
    uint32_t ahr[2][4], ahi[2][4], bpr[4], bpi[4];
    #pragma unroll
    for (int mt = 0; mt < 2; mt++) {
        LDSM_X4(ahr[mt], aCr + mt * 16 * 80);
        LDSM_X4(ahi[mt], aCi + mt * 16 * 80);
    }
    LDSM_X4(bpr, bPr);
    LDSM_X4(bpi, bPi);
    #pragma unroll
    for (int mt = 0; mt < 2; mt++) {
        #pragma unroll
        for (int nt = 0; nt < 2; nt++) {
            int q = nt * 2;
            MMAF16(Srr[mt][nt], ahr[mt], bpr[q], bpr[q+1]);
            MMAF16(Sri[mt][nt], ahr[mt], bpi[q], bpi[q+1]);
            MMAF16(Sir[mt][nt], ahi[mt], bpr[q], bpr[q+1]);
            MMAF16(Sii[mt][nt], ahi[mt], bpi[q], bpi[q+1]);
        }
    }
}

// ---------------- main kernel ----------------
__global__ void __launch_bounds__(NT, 2)
mma_kernel(const float* __restrict__ r, const float* __restrict__ kg,
           float* __restrict__ out, int out_elems)
{
    extern __shared__ char smem[];
    uint32_t sb = smem_u32(smem);
    const int tid  = threadIdx.x;
    const int wid  = tid >> 5;
    const int lane = tid & 31;
    const int p0   = blockIdx.x * NTILE;
    const uint32_t mbar0 = sb + MB_OFF;
    const uint32_t mbar1 = sb + MB_OFF + 8;

    // e tables: se[(d*32+p)*20+i] = exp(i * m(i) * (B_d . r_p))
    float2* se = (float2*)(smem + SE_OFF);
    for (int t = tid; t < 3 * NTILE * NGR; t += NT) {
        int d   = t / (NTILE * NGR);
        int rem = t - d * NTILE * NGR;
        int p   = rem / NGR;
        int i   = rem - p * NGR;
        int m   = (i < NGR/2) ? i : i - NGR;
        const float* rp = r + (p0 + p) * 3;
        float u = d_B[3*d]*rp[0] + d_B[3*d+1]*rp[1] + d_B[3*d+2]*rp[2];
        float sv, cv;
        sincosf((float)m * u, &sv, &cv);
        se[(d * NTILE + p) * NGR + i] = make_float2(cv, sv);
    }
    if (tid == 0) {
        asm volatile("mbarrier.init.shared.b64 [%0], %1;" :: "r"(mbar0), "r"(1u) : "memory");
        asm volatile("mbarrier.init.shared.b64 [%0], %1;" :: "r"(mbar1), "r"(1u) : "memory");
    }
    __syncthreads();

    // prologue: issue A(0) copy; generate B(0); sync
    if (tid == 0) {
        asm volatile("mbarrier.arrive.expect_tx.shared.b64 _, [%0], %1;"
                     :: "r"(mbar0), "r"((uint32_t)STG_BYTES) : "memory");
        asm volatile("cp.async.bulk.shared::cluster.global.mbarrier::complete_tx::bytes [%0], [%1], %2, [%3];"
                     :: "r"(sb), "l"((const char*)d_A2), "r"((uint32_t)STG_BYTES), "r"(mbar0) : "memory");
    }
    bgen(smem, se, 0, wid, lane);
    __syncthreads();

    // accumulators: Srr=cr*pr, Sri=cr*pi, Sir=ci*pr, Sii=ci*pi
    float Srr[2][2][4], Sri[2][2][4], Sir[2][2][4], Sii[2][2][4];
    #pragma unroll
    for (int mt = 0; mt < 2; mt++)
        #pragma unroll
        for (int nt = 0; nt < 2; nt++)
            #pragma unroll
            for (int q = 0; q < 4; q++) {
                Srr[mt][nt][q]=0.f; Sri[mt][nt][q]=0.f;
                Sir[mt][nt][q]=0.f; Sii[mt][nt][q]=0.f;
            }

    // per-thread ldmatrix row offsets
    const uint32_t aRowOff = (lane & 15) * 80 + (lane >> 4) * 16;
    const uint32_t bRowOff = (((lane >> 4) & 1) * 8 + (lane & 7)) * 80 + ((lane >> 3) & 1) * 16;
    const int m0 = (wid & 3) * 32;    // 4 m-warps
    const int n0 = (wid >> 2) * 16;   // 2 n-warps
    const uint32_t amBase = (uint32_t)m0 * 80 + aRowOff;
    const uint32_t bnBase = (uint32_t)n0 * 80 + bRowOff;

    for (int s = 0; s < NSTAGE; s++) {
        const int cur = s & 1;
        const uint32_t aBuf = sb + cur * STG_BYTES;
        const uint32_t bBuf = sb + B_OFF + cur * BS_BUF;

        // ---- issue bulk copy for stage s+1 into the other A buffer ----
        if (tid == 0 && s + 1 < NSTAGE) {
            uint32_t nb = (s + 1) & 1;
            uint32_t mb = nb ? mbar1 : mbar0;
            asm volatile("mbarrier.arrive.expect_tx.shared.b64 _, [%0], %1;"
                         :: "r"(mb), "r"((uint32_t)STG_BYTES) : "memory");
            const char* src = (const char*)d_A2 + (size_t)(s + 1) * STG_BYTES;
            asm volatile("cp.async.bulk.shared::cluster.global.mbarrier::complete_tx::bytes [%0], [%1], %2, [%3];"
                         :: "r"(sb + nb * STG_BYTES), "l"(src), "r"((uint32_t)STG_BYTES), "r"(mb) : "memory");
        }

        // ---- wait for A(s), then issue the MMA burst ----
        MBAR_WAIT(cur ? mbar1 : mbar0, (uint32_t)((s >> 1) & 1));

        #pragma unroll
        for (int k16 = 0; k16 < 2; k16++) {
            uint32_t kb = k16 * 32;
            mma_quad(Srr, Sri, Sir, Sii,
                     aBuf + 0*AS_VAR + amBase + kb,
                     aBuf + 1*AS_VAR + amBase + kb,
                     bBuf + 0*BS_VAR + bnBase + kb,
                     bBuf + 1*BS_VAR + bnBase + kb);
        }

        // ---- generate B(s+1) behind the MMA burst ----
        if (s + 1 < NSTAGE)
            bgen(smem, se, s + 1, wid, lane);

        __syncthreads();   // MMA(s) done + B(s+1) visible everywhere
    }

    // ---- epilogue: Re = Srr - Sii, Im = Sri + Sir; rotate by k, scale, store ----
    const bool cplx = (out_elems >= 2 * NB * NPTS);
    const float scale = d_scale;
    #pragma unroll
    for (int mt = 0; mt < 2; mt++) {
        #pragma unroll
        for (int nt = 0; nt < 2; nt++) {
            #pragma unroll
            for (int q = 0; q < 4; q++) {
                float Re = Srr[mt][nt][q] - Sii[mt][nt][q];
                float Im = Sri[mt][nt][q] + Sir[mt][nt][q];
                int b = m0 + mt * 16 + (lane >> 2) + (q >> 1) * 8;
                int p = p0 + n0 + nt * 8 + (lane & 3) * 2 + (q & 1);
                int kq = (b >> 4) & 3;
                const float* rp = r + p * 3;
                float ang = kg[3*kq]*rp[0] + kg[3*kq+1]*rp[1] + kg[3*kq+2]*rp[2];
                float sv, cv;
                sincosf(ang, &sv, &cv);
                float ore = (Re * cv - Im * sv) * scale;
                float oim = (Re * sv + Im * cv) * scale;
                size_t idx = (size_t)b * NPTS + p;
                if (cplx) ((float2*)out)[idx] = make_float2(ore, oim);
                else      out[idx] = ore;
            }
        }
    }
}

extern "C" void kernel_launch(void* const* d_in, const int* in_sizes, int n_in,
                              void* d_out, int out_size) {
    const float* A   = nullptr;
    const float* kg  = nullptr;
    const float* r   = nullptr;
    const float* cre = nullptr;
    const float* cim = nullptr;
    for (int i = 0; i < n_in; i++) {
        const float* p = (const float*)d_in[i];
        long long sz = in_sizes[i];
        if (sz == 9 || sz == 36)               A = p;
        else if (sz == 12 || sz == 48)         kg = p;
        else if (sz == 24000 || sz == 96000)   r = p;
        else if (sz == (long long)NB * NG || sz == (long long)NB * NG * 4) {
            if (!cre) cre = p; else cim = p;
        }
    }
    if (!A || !kg || !r || !cre || !cim) {
        if (n_in >= 5) {
            A   = (const float*)d_in[0];
            kg  = (const float*)d_in[1];
            cre = (const float*)d_in[2];
            cim = (const float*)d_in[3];
            r   = (const float*)d_in[4];
        } else {
            return;
        }
    }

    static bool attr_set = false;
    if (!attr_set) {
        cudaFuncSetAttribute(mma_kernel, cudaFuncAttributeMaxDynamicSharedMemorySize, SM_TOTAL);
        attr_set = true;
    }

    prep_kernel<<<NB, 256>>>(cre, cim, A);
    mma_kernel<<<NCTA, NT, SM_TOTAL>>>(r, kg, (float*)d_out, out_size);
}

// round 17
// speedup vs baseline: 2.9584x; 1.1577x over previous
#include <cuda_runtime.h>
#include <cuda_fp16.h>
#include <math.h>
#include <stdint.h>

#define NB     128     // batches
#define NG     8000    // plane waves (20^3)
#define NPTS   8000    // points
#define NGR    20      // grid per dim
#define KC     64      // K per stage
#define NSTAGE 125     // NG / KC
#define NTILE  32      // points per CTA
#define NCTA   250     // NPTS / NTILE
#define NT     256     // threads (8 warps, 4m x 2n grid: m32 x n16 per warp)

// Row stride: 128B data + 16B pad = 144B (ldmatrix conflict-free: 144 mod 128 = 16)
#define ROWB      144
#define AS_VAR    18432                      // 128 rows x 144B
#define STG_BYTES 36864                      // 2 variants x AS_VAR
#define B_OFF     73728                      // after 2 A buffers
#define BS_VAR    4608                       // 32 rows x 144B
#define BS_BUF    9216                       // 2 variants
#define SE_OFF    92160                      // 3 x 32 x 20 x float2 = 15360
#define MB_OFF    107520                     // 2 mbarriers
#define SM_TOTAL  107552

__device__ float d_B[9];
__device__ float d_scale;
// stage-major, ldmatrix-ready (144B rows = 72 halfs, pad zeroed), fp16:
// d_A2[((s*2 + v)*128 + row)*72 + g]   v: 0 cr  1 ci
__device__ __align__(128) __half d_A2[(size_t)NSTAGE * 2 * NB * 72];  // 4.6 MB

// ---------------- helpers ----------------
__device__ __forceinline__ uint32_t smem_u32(const void* p) {
    uint32_t a;
    asm("{ .reg .u64 t; cvta.to.shared.u64 t, %1; cvt.u32.u64 %0, t; }" : "=r"(a) : "l"(p));
    return a;
}
__device__ __forceinline__ float2 cmul(float2 a, float2 b) {
    return make_float2(a.x*b.x - a.y*b.y, a.x*b.y + a.y*b.x);
}

#define MMAF16(d, a, b0, b1) \
    asm volatile("mma.sync.aligned.m16n8k16.row.col.f32.f16.f16.f32 " \
        "{%0,%1,%2,%3}, {%4,%5,%6,%7}, {%8,%9}, {%0,%1,%2,%3};" \
        : "+f"((d)[0]), "+f"((d)[1]), "+f"((d)[2]), "+f"((d)[3]) \
        : "r"((a)[0]), "r"((a)[1]), "r"((a)[2]), "r"((a)[3]), "r"(b0), "r"(b1))

#define LDSM_X4(r, addr) \
    asm volatile("ldmatrix.sync.aligned.m8n8.x4.shared.b16 {%0,%1,%2,%3}, [%4];" \
        : "=r"((r)[0]), "=r"((r)[1]), "=r"((r)[2]), "=r"((r)[3]) : "r"(addr))

#define MBAR_WAIT(mbar, parity) do { \
    uint32_t _m = (mbar); uint32_t _p = (parity); uint32_t _d; \
    asm volatile("{ .reg .pred p; mbarrier.try_wait.parity.acquire.cta.shared::cta.b64 p, [%1], %2; selp.b32 %0, 1, 0, p; }" \
        : "=r"(_d) : "r"(_m), "r"(_p) : "memory"); \
    if (!_d) { \
        asm volatile("{ .reg .pred P1; WL_%=: mbarrier.try_wait.parity.acquire.cta.shared::cta.b64 P1, [%0], %1, 0x989680; @P1 bra.uni WD_%=; bra.uni WL_%=; WD_%=: }" \
            :: "r"(_m), "r"(_p) : "memory"); \
    } \
} while (0)

// ---------------- prep: setup (block 0) + stage-major fp16 coefficients ----------------
__global__ void prep_kernel(const float* __restrict__ cre, const float* __restrict__ cim,
                            const float* __restrict__ A) {
    if (blockIdx.x == 0 && threadIdx.x == 0) {
        double a00=A[0],a01=A[1],a02=A[2];
        double a10=A[3],a11=A[4],a12=A[5];
        double a20=A[6],a21=A[7],a22=A[8];
        double c00 =  (a11*a22 - a12*a21);
        double c01 = -(a10*a22 - a12*a20);
        double c02 =  (a10*a21 - a11*a20);
        double c10 = -(a01*a22 - a02*a21);
        double c11 =  (a00*a22 - a02*a20);
        double c12 = -(a00*a21 - a01*a20);
        double c20 =  (a01*a12 - a02*a11);
        double c21 = -(a00*a12 - a02*a10);
        double c22 =  (a00*a11 - a01*a10);
        double det = a00*c00 + a01*c01 + a02*c02;
        double tp  = 6.283185307179586476925286766559;
        double s   = tp / det;
        d_B[0]=(float)(c00*s); d_B[1]=(float)(c01*s); d_B[2]=(float)(c02*s);
        d_B[3]=(float)(c10*s); d_B[4]=(float)(c11*s); d_B[5]=(float)(c12*s);
        d_B[6]=(float)(c20*s); d_B[7]=(float)(c21*s); d_B[8]=(float)(c22*s);
        d_scale = (float)(1.0 / sqrt(fabs(det)));
    }
    int b = blockIdx.x;
    for (int g = threadIdx.x; g < NG; g += 256) {
        int s  = g >> 6;
        int gl = g & 63;
        size_t base = ((size_t)s * 2 * NB + b) * 72 + gl;
        d_A2[base]                    = __float2half(cre[(size_t)b * NG + g]);
        d_A2[base + (size_t)NB * 72]  = __float2half(cim[(size_t)b * NG + g]);
    }
    // zero the 16B row padding (halfs 64..71; deterministic every call)
    __half z = __float2half(0.0f);
    for (int t = threadIdx.x; t < NSTAGE * 2 * 8; t += 256) {
        int s = t / 16;
        int rem = t - s * 16;
        int v = rem >> 3;
        int q = rem & 7;
        d_A2[(((size_t)s * 2 + v) * NB + b) * 72 + 64 + q] = z;
    }
}

// ---------------- B phase generation (2 variants, 4 pts/warp, 64 g's in 2 halves) ----------------
__device__ __forceinline__ void bgen(char* smem, const float2* se, int s,
                                     int wid, int lane)
{
    char* bptr = smem + B_OFF + (s & 1) * BS_BUF;
    #pragma unroll
    for (int h = 0; h < 2; h++) {
        int gl = h * 32 + lane;
        int g  = s * KC + gl;
        int i1 = g / 400;
        int i2 = (g / 20) % 20;
        int i3 = g % 20;
        #pragma unroll
        for (int pi = 0; pi < 4; pi++) {
            int p = wid * 4 + pi;
            float2 e1 = se[(0 * NTILE + p) * NGR + i1];
            float2 e2 = se[(1 * NTILE + p) * NGR + i2];
            float2 e3 = se[(2 * NTILE + p) * NGR + i3];
            float2 ph = cmul(cmul(e1, e2), e3);
            uint32_t off = (uint32_t)p * ROWB + gl * 2;
            *(__half*)(bptr + 0 * BS_VAR + off) = __float2half(ph.x);
            *(__half*)(bptr + 1 * BS_VAR + off) = __float2half(ph.y);
        }
    }
}

// ---------------- mma block: one k16, 4 product sets with operand reuse ----------------
__device__ __forceinline__ void mma_quad(
    float Srr[2][2][4], float Sri[2][2][4], float Sir[2][2][4], float Sii[2][2][4],
    uint32_t aCr, uint32_t aCi, uint32_t bPr, uint32_t bPi)
{
    uint32_t ahr[2][4], ahi[2][4], bpr[4], bpi[4];
    #pragma unroll
    for (int mt = 0; mt < 2; mt++) {
        LDSM_X4(ahr[mt], aCr + mt * 16 * ROWB);
        LDSM_X4(ahi[mt], aCi + mt * 16 * ROWB);
    }
    LDSM_X4(bpr, bPr);
    LDSM_X4(bpi, bPi);
    #pragma unroll
    for (int mt = 0; mt < 2; mt++) {
        #pragma unroll
        for (int nt = 0; nt < 2; nt++) {
            int q = nt * 2;
            MMAF16(Srr[mt][nt], ahr[mt], bpr[q], bpr[q+1]);
            MMAF16(Sri[mt][nt], ahr[mt], bpi[q], bpi[q+1]);
            MMAF16(Sir[mt][nt], ahi[mt], bpr[q], bpr[q+1]);
            MMAF16(Sii[mt][nt], ahi[mt], bpi[q], bpi[q+1]);
        }
    }
}

// ---------------- main kernel ----------------
__global__ void __launch_bounds__(NT, 2)
mma_kernel(const float* __restrict__ r, const float* __restrict__ kg,
           float* __restrict__ out, int out_elems)
{
    extern __shared__ char smem[];
    uint32_t sb = smem_u32(smem);
    const int tid  = threadIdx.x;
    const int wid  = tid >> 5;
    const int lane = tid & 31;
    const int p0   = blockIdx.x * NTILE;
    const uint32_t mbar0 = sb + MB_OFF;
    const uint32_t mbar1 = sb + MB_OFF + 8;

    // e tables: se[(d*32+p)*20+i] = exp(i * m(i) * (B_d . r_p))
    float2* se = (float2*)(smem + SE_OFF);
    for (int t = tid; t < 3 * NTILE * NGR; t += NT) {
        int d   = t / (NTILE * NGR);
        int rem = t - d * NTILE * NGR;
        int p   = rem / NGR;
        int i   = rem - p * NGR;
        int m   = (i < NGR/2) ? i : i - NGR;
        const float* rp = r + (p0 + p) * 3;
        float u = d_B[3*d]*rp[0] + d_B[3*d+1]*rp[1] + d_B[3*d+2]*rp[2];
        float sv, cv;
        sincosf((float)m * u, &sv, &cv);
        se[(d * NTILE + p) * NGR + i] = make_float2(cv, sv);
    }
    if (tid == 0) {
        asm volatile("mbarrier.init.shared.b64 [%0], %1;" :: "r"(mbar0), "r"(1u) : "memory");
        asm volatile("mbarrier.init.shared.b64 [%0], %1;" :: "r"(mbar1), "r"(1u) : "memory");
    }
    __syncthreads();

    // prologue: issue A(0) copy; generate B(0); sync
    if (tid == 0) {
        asm volatile("mbarrier.arrive.expect_tx.shared.b64 _, [%0], %1;"
                     :: "r"(mbar0), "r"((uint32_t)STG_BYTES) : "memory");
        asm volatile("cp.async.bulk.shared::cluster.global.mbarrier::complete_tx::bytes [%0], [%1], %2, [%3];"
                     :: "r"(sb), "l"((const char*)d_A2), "r"((uint32_t)STG_BYTES), "r"(mbar0) : "memory");
    }
    bgen(smem, se, 0, wid, lane);
    __syncthreads();

    // accumulators: Srr=cr*pr, Sri=cr*pi, Sir=ci*pr, Sii=ci*pi
    float Srr[2][2][4], Sri[2][2][4], Sir[2][2][4], Sii[2][2][4];
    #pragma unroll
    for (int mt = 0; mt < 2; mt++)
        #pragma unroll
        for (int nt = 0; nt < 2; nt++)
            #pragma unroll
            for (int q = 0; q < 4; q++) {
                Srr[mt][nt][q]=0.f; Sri[mt][nt][q]=0.f;
                Sir[mt][nt][q]=0.f; Sii[mt][nt][q]=0.f;
            }

    // per-thread ldmatrix row offsets (row stride 144B)
    const uint32_t aRowOff = (lane & 15) * ROWB + (lane >> 4) * 16;
    const uint32_t bRowOff = (((lane >> 4) & 1) * 8 + (lane & 7)) * ROWB + ((lane >> 3) & 1) * 16;
    const int m0 = (wid & 3) * 32;    // 4 m-warps
    const int n0 = (wid >> 2) * 16;   // 2 n-warps
    const uint32_t amBase = (uint32_t)m0 * ROWB + aRowOff;
    const uint32_t bnBase = (uint32_t)n0 * ROWB + bRowOff;

    for (int s = 0; s < NSTAGE; s++) {
        const int cur = s & 1;
        const uint32_t aBuf = sb + cur * STG_BYTES;
        const uint32_t bBuf = sb + B_OFF + cur * BS_BUF;

        // ---- issue bulk copy for stage s+1 into the other A buffer ----
        if (tid == 0 && s + 1 < NSTAGE) {
            uint32_t nb = (s + 1) & 1;
            uint32_t mb = nb ? mbar1 : mbar0;
            asm volatile("mbarrier.arrive.expect_tx.shared.b64 _, [%0], %1;"
                         :: "r"(mb), "r"((uint32_t)STG_BYTES) : "memory");
            const char* src = (const char*)d_A2 + (size_t)(s + 1) * STG_BYTES;
            asm volatile("cp.async.bulk.shared::cluster.global.mbarrier::complete_tx::bytes [%0], [%1], %2, [%3];"
                         :: "r"(sb + nb * STG_BYTES), "l"(src), "r"((uint32_t)STG_BYTES), "r"(mb) : "memory");
        }

        // ---- wait for A(s), then issue the MMA burst (4 k16 steps) ----
        MBAR_WAIT(cur ? mbar1 : mbar0, (uint32_t)((s >> 1) & 1));

        #pragma unroll
        for (int k16 = 0; k16 < 4; k16++) {
            uint32_t kb = k16 * 32;
            mma_quad(Srr, Sri, Sir, Sii,
                     aBuf + 0*AS_VAR + amBase + kb,
                     aBuf + 1*AS_VAR + amBase + kb,
                     bBuf + 0*BS_VAR + bnBase + kb,
                     bBuf + 1*BS_VAR + bnBase + kb);
        }

        // ---- generate B(s+1) behind the MMA burst ----
        if (s + 1 < NSTAGE)
            bgen(smem, se, s + 1, wid, lane);

        __syncthreads();   // MMA(s) done + B(s+1) visible everywhere
    }

    // ---- epilogue: Re = Srr - Sii, Im = Sri + Sir; rotate by k, scale, store ----
    const bool cplx = (out_elems >= 2 * NB * NPTS);
    const float scale = d_scale;
    #pragma unroll
    for (int mt = 0; mt < 2; mt++) {
        #pragma unroll
        for (int nt = 0; nt < 2; nt++) {
            #pragma unroll
            for (int q = 0; q < 4; q++) {
                float Re = Srr[mt][nt][q] - Sii[mt][nt][q];
                float Im = Sri[mt][nt][q] + Sir[mt][nt][q];
                int b = m0 + mt * 16 + (lane >> 2) + (q >> 1) * 8;
                int p = p0 + n0 + nt * 8 + (lane & 3) * 2 + (q & 1);
                int kq = (b >> 4) & 3;
                const float* rp = r + p * 3;
                float ang = kg[3*kq]*rp[0] + kg[3*kq+1]*rp[1] + kg[3*kq+2]*rp[2];
                float sv, cv;
                sincosf(ang, &sv, &cv);
                float ore = (Re * cv - Im * sv) * scale;
                float oim = (Re * sv + Im * cv) * scale;
                size_t idx = (size_t)b * NPTS + p;
                if (cplx) ((float2*)out)[idx] = make_float2(ore, oim);
                else      out[idx] = ore;
            }
        }
    }
}

extern "C" void kernel_launch(void* const* d_in, const int* in_sizes, int n_in,
                              void* d_out, int out_size) {
    const float* A   = nullptr;
    const float* kg  = nullptr;
    const float* r   = nullptr;
    const float* cre = nullptr;
    const float* cim = nullptr;
    for (int i = 0; i < n_in; i++) {
        const float* p = (const float*)d_in[i];
        long long sz = in_sizes[i];
        if (sz == 9 || sz == 36)               A = p;
        else if (sz == 12 || sz == 48)         kg = p;
        else if (sz == 24000 || sz == 96000)   r = p;
        else if (sz == (long long)NB * NG || sz == (long long)NB * NG * 4) {
            if (!cre) cre = p; else cim = p;
        }
    }
    if (!A || !kg || !r || !cre || !cim) {
        if (n_in >= 5) {
            A   = (const float*)d_in[0];
            kg  = (const float*)d_in[1];
            cre = (const float*)d_in[2];
            cim = (const float*)d_in[3];
            r   = (const float*)d_in[4];
        } else {
            return;
        }
    }

    static bool attr_set = false;
    if (!attr_set) {
        cudaFuncSetAttribute(mma_kernel, cudaFuncAttributeMaxDynamicSharedMemorySize, SM_TOTAL);
        attr_set = true;
    }

    prep_kernel<<<NB, 256>>>(cre, cim, A);
    mma_kernel<<<NCTA, NT, SM_TOTAL>>>(r, kg, (float*)d_out, out_size);
}